// round 12
// baseline (speedup 1.0000x reference)
#include <cuda_runtime.h>
#include <cuda_fp16.h>
#include <cstdint>

#define NT 4096

// ===================== device scratch (no allocs) ============================
__device__ __half g_xin2[NT * 1024];         // x input split: hi 0..511 | lo 512..1023
__device__ __half g_fcwT2[256 * 1024];       // fc_w^T split
__device__ __half g_wcatT2[2][768 * 512];    // rows: [wq(256)|wk'(256)|wcomb(256)], split cols
__device__ __half g_wvl2[2][256 * 512];      // wvl rows split (for wcomb prep GEMM)
__device__ __half g_dwT2[2][256 * 512];      // (wvg0-wvg1)^T split
__device__ float g_bcat[2][768];             // [bq | bk' | bcomb]
__device__ float g_bp[2][16][256];           // bcomb partials
__device__ __half g_xs[NT * 512];            // current x split: hi 0..255 | lo 256..511
__device__ __half g_qk[NT * 1536];           // [qh kh (unused) | lo region dead]
__device__ __half g_Dt[256 * 8192];          // D^T: hi 0..4095 (lo region dead)
__device__ __half g_W[(size_t)NT * 4096];    // sigmoid W, single fp16
__device__ float g_part[8][NT * 256];        // split-K partials
__device__ float g_cs[64 * 256];
__device__ float g_c[256];

// ===================== helpers ===============================================
__device__ __forceinline__ uint32_t s2u(const void* p) {
    uint32_t a;
    asm("{ .reg .u64 t; cvta.to.shared.u64 t, %1; cvt.u32.u64 %0, t; }"
        : "=r"(a) : "l"(p));
    return a;
}

#define CP_ASYNC16(saddr, gaddr) \
    asm volatile("cp.async.cg.shared.global [%0], [%1], 16;" \
                 :: "r"(saddr), "l"(gaddr) : "memory")
#define CP_COMMIT() asm volatile("cp.async.commit_group;" ::: "memory")
#define CP_WAIT0() asm volatile("cp.async.wait_group 0;" ::: "memory")

#define LDSM_X4(r0, r1, r2, r3, addr) \
    asm volatile("ldmatrix.sync.aligned.m8n8.x4.shared.b16 {%0,%1,%2,%3}, [%4];" \
                 : "=r"(r0), "=r"(r1), "=r"(r2), "=r"(r3) : "r"(addr))

#define MMA16816(d, a0, a1, a2, a3, b0, b1) \
    asm volatile("mma.sync.aligned.m16n8k16.row.col.f32.f16.f16.f32 " \
                 "{%0,%1,%2,%3}, {%4,%5,%6,%7}, {%8,%9}, {%0,%1,%2,%3};" \
                 : "+f"((d)[0]), "+f"((d)[1]), "+f"((d)[2]), "+f"((d)[3]) \
                 : "r"(a0), "r"(a1), "r"(a2), "r"(a3), "r"(b0), "r"(b1))

// ===================== fast sigmoid via tanh.approx ==========================
__device__ __forceinline__ float sigmoid_tanh(float s_halfscaled) {
    float t;
    asm("tanh.approx.f32 %0, %1;" : "=f"(t) : "f"(s_halfscaled));
    return fmaf(0.5f, t, 0.5f);
}

// ===================== generic HMMA fp16 split GEMM ==========================
// Tile 128x64, pair-stage mainloop (2x BK=32 per barrier), 4-buffer ring,
// 80B padded rows, 8 warps (2m x 4n), warp tile 64x16, 3 CTAs/SM.
// kcount must be a multiple of 64.
// modes: 0 raw fp32(+bias) -> Cf; 1 (bias?)+fp16 -> Cb; 2 sigmoid fp16 -> Cb;
// 4 fp32 partial -> Cf + z*4096*256; 5 combo: n0<nSplit mode1 else transposed.
#define ROWB 80                  // 32 fp16 = 64B data + 16B pad
#define ATILEB (128 * ROWB)      // 10240
#define BTILEB (64 * ROWB)       // 5120
#define STAGEB (ATILEB + BTILEB) // 15360
#define SMEM_DYN (4 * STAGEB)    // 61440

__global__ __launch_bounds__(256, 3)
void tc_gemm(const __half* __restrict__ A, int lda, int aO0, int aO1, int aO2,
             const __half* __restrict__ B, int ldb, int bO0, int bO1, int bO2,
             int Kreg, int kcount, const float* __restrict__ bias,
             float* __restrict__ Cf, int ldc,
             __half* __restrict__ Cb, int ldcb,
             int mode, int nSplit, float scale) {
    extern __shared__ __align__(16) char dsm[];
    const int tid = threadIdx.x;
    const int wid = tid >> 5, lane = tid & 31;
    const int wm = wid & 1, wn = wid >> 1;          // 2m x 4n warp grid
    const int m0 = blockIdx.x * 128, n0 = blockIdx.y * 64;
    const int kbase = blockIdx.z * kcount;
    const int P = kcount >> 6;                      // pairs of 32-K stages
    const int aO[3] = {aO0, aO1, aO2};
    const int bO[3] = {bO0, bO1, bO2};

    const uint32_t sbase = s2u(dsm);
    const int arow = tid & 127, ach0 = tid >> 7;    // A loader mapping
    const int brow = tid & 63, bch = tid >> 6;      // B loader mapping

    auto load_stage = [&](int buf, int kglob) {
        int region = kglob / Kreg;
        int off = kglob - region * Kreg;
        const __half* Ap = A + (size_t)(m0 + arow) * lda + aO[region] + off;
        const __half* Bp = B + (size_t)(n0 + brow) * ldb + bO[region] + off;
        uint32_t sa = sbase + buf * STAGEB + arow * ROWB;
        uint32_t sb = sbase + buf * STAGEB + ATILEB + brow * ROWB;
#pragma unroll
        for (int p = 0; p < 2; p++) {
            int ch = ach0 + 2 * p;  // 0..3
            CP_ASYNC16(sa + ch * 16, (const char*)(Ap + ch * 8));
        }
        CP_ASYNC16(sb + bch * 16, (const char*)(Bp + bch * 8));
    };

    float acc[4][2][4];
#pragma unroll
    for (int i = 0; i < 4; i++)
#pragma unroll
        for (int j = 0; j < 2; j++)
#pragma unroll
            for (int e = 0; e < 4; e++) acc[i][j][e] = 0.f;

    load_stage(0, kbase);
    load_stage(1, kbase + 32);
    CP_COMMIT();

    // A frag: per mt (16 rows), lanes 0-15 rows, lanes 16-31 k+8 half
    const uint32_t a_frag_off = (wm * 64 + (lane & 15)) * ROWB + (lane >> 4) * 16;
    // B frag: paired x4 over both nt (16 rows): lanes 0-7 nt0 rows khalf0,
    // 8-15 nt0 khalf1, 16-23 nt1 rows khalf0, 24-31 nt1 khalf1
    const uint32_t b_frag_off =
        (wn * 16 + (lane & 7) + ((lane >> 4) << 3)) * ROWB + ((lane >> 3) & 1) * 16;

    for (int p = 0; p < P; p++) {
        CP_WAIT0();
        __syncthreads();
        if (p + 1 < P) {
            int nb = ((p + 1) & 1) * 2;
            load_stage(nb, kbase + (p + 1) * 64);
            load_stage(nb + 1, kbase + (p + 1) * 64 + 32);
            CP_COMMIT();
        }
        const int pb = (p & 1) * 2;
#pragma unroll
        for (int j = 0; j < 2; j++) {
            const uint32_t sa = sbase + (pb + j) * STAGEB;
            const uint32_t sb = sa + ATILEB;
#pragma unroll
            for (int kk = 0; kk < 2; kk++) {
                uint32_t af[4][4], bf[4];
                LDSM_X4(bf[0], bf[1], bf[2], bf[3], sb + b_frag_off + kk * 32);
#pragma unroll
                for (int mt = 0; mt < 4; mt++)
                    LDSM_X4(af[mt][0], af[mt][1], af[mt][2], af[mt][3],
                            sa + a_frag_off + mt * (16 * ROWB) + kk * 32);
#pragma unroll
                for (int mt = 0; mt < 4; mt++) {
                    MMA16816(acc[mt][0], af[mt][0], af[mt][1], af[mt][2], af[mt][3],
                             bf[0], bf[1]);
                    MMA16816(acc[mt][1], af[mt][0], af[mt][1], af[mt][2], af[mt][3],
                             bf[2], bf[3]);
                }
            }
        }
    }

    // ---- epilogue ----
    const int tr = lane >> 2, tc = lane & 3;
    const int mbase = m0 + wm * 64 + tr;
    const int nbase = n0 + wn * 16 + tc * 2;

    int emode = mode;
    if (mode == 5) emode = (n0 >= nSplit) ? 3 : 1;

    if (emode == 0 || emode == 4) {
        float* base = Cf + (emode == 4 ? (size_t)blockIdx.z * (4096 * 256) : 0);
#pragma unroll
        for (int mt = 0; mt < 4; mt++)
#pragma unroll
            for (int h = 0; h < 2; h++) {
                int m = mbase + mt * 16 + h * 8;
                float* rowp = base + (size_t)m * ldc;
#pragma unroll
                for (int nt = 0; nt < 2; nt++) {
                    int n = nbase + nt * 8;
                    float v0 = acc[mt][nt][2 * h + 0];
                    float v1 = acc[mt][nt][2 * h + 1];
                    if (bias) { v0 += bias[n]; v1 += bias[n + 1]; }
                    *(float2*)(rowp + n) = make_float2(v0, v1);
                }
            }
    } else if (emode == 1) {
#pragma unroll
        for (int mt = 0; mt < 4; mt++)
#pragma unroll
            for (int h = 0; h < 2; h++) {
                int m = mbase + mt * 16 + h * 8;
                __half* rowp = Cb + (size_t)m * ldcb;
#pragma unroll
                for (int nt = 0; nt < 2; nt++) {
                    int n = nbase + nt * 8;
                    float v0 = acc[mt][nt][2 * h + 0];
                    float v1 = acc[mt][nt][2 * h + 1];
                    if (bias) { v0 += bias[n]; v1 += bias[n + 1]; }
                    *(__half2*)(rowp + n) =
                        __halves2half2(__float2half_rn(v0), __float2half_rn(v1));
                }
            }
    } else if (emode == 2) {
#pragma unroll
        for (int mt = 0; mt < 4; mt++)
#pragma unroll
            for (int h = 0; h < 2; h++) {
                int m = mbase + mt * 16 + h * 8;
                __half* rowp = Cb + (size_t)m * ldcb;
#pragma unroll
                for (int nt = 0; nt < 2; nt++) {
                    int n = nbase + nt * 8;
                    float v0 = sigmoid_tanh(scale * acc[mt][nt][2 * h + 0]);
                    float v1 = sigmoid_tanh(scale * acc[mt][nt][2 * h + 1]);
                    *(__half2*)(rowp + n) =
                        __halves2half2(__float2half_rn(v0), __float2half_rn(v1));
                }
            }
    } else {  // emode 3: transposed fp16 into (half*)Cf, ld=ldc
        __half* Ct = (__half*)Cf;
#pragma unroll
        for (int mt = 0; mt < 4; mt++)
#pragma unroll
            for (int h = 0; h < 2; h++) {
                int m = mbase + mt * 16 + h * 8;
#pragma unroll
                for (int nt = 0; nt < 2; nt++) {
                    int n = nbase + nt * 8;
#pragma unroll
                    for (int e = 0; e < 2; e++) {
                        float v = acc[mt][nt][2 * h + e] + bias[n + e];
                        Ct[(size_t)(n + e - nSplit) * ldc + m] = __float2half_rn(v);
                    }
                }
            }
    }
}

// ===================== prep kernels ==========================================
__device__ __forceinline__ void split_store(__half* hi, __half* lo, float v) {
    __half h = __float2half_rn(v);
    *hi = h;
    *lo = __float2half_rn(v - __half2float(h));
}

// Segmented prep kernel. blocks: [0,4096) x | [4096,4352) fcw | [4352,5376)
// wcat | [5376,5888) wvl | [5888,6400) dw
__global__ void prep_main(const float* __restrict__ x, const float* __restrict__ fcw,
                          const float* __restrict__ wq, const float* __restrict__ wk,
                          const float* __restrict__ wvl, const float* __restrict__ wvg) {
    int b = blockIdx.x, t = threadIdx.x;
    if (b < 4096) {
        int row = b;
#pragma unroll
        for (int i = 0; i < 2; i++) {
            int c = t + i * 256;
            split_store(&g_xin2[row * 1024 + c], &g_xin2[row * 1024 + 512 + c],
                        x[row * 512 + c]);
        }
    } else if (b < 4352) {
        int n = b - 4096;
#pragma unroll
        for (int i = 0; i < 2; i++) {
            int k = t + i * 256;
            split_store(&g_fcwT2[n * 1024 + k], &g_fcwT2[n * 1024 + 512 + k],
                        fcw[k * 256 + n]);
        }
    } else if (b < 5376) {
        int idx = b - 4352, l = idx >> 9, n = idx & 511, k = t;
        float v;
        if (n < 256) v = wq[(l * 256 + k) * 256 + n];
        else {
            float s = wk[(l * 256 + k) * 256 + (n - 256)];
            v = (n - 256 < 128) ? s : -s;
        }
        split_store(&g_wcatT2[l][n * 512 + k], &g_wcatT2[l][n * 512 + 256 + k], v);
    } else if (b < 5888) {
        int idx = b - 5376, l = idx >> 8, k = idx & 255, j = t;
        float v = wvl[(l * 256 + k) * 256 + j];
        split_store(&g_wvl2[l][k * 512 + j], &g_wvl2[l][k * 512 + 256 + j], v);
    } else {
        int idx = b - 5888, l = idx >> 8, n = idx & 255, k = t;
        float v = wvg[(l * 256 + k) * 512 + n] - wvg[(l * 256 + k) * 512 + 256 + n];
        split_store(&g_dwT2[l][n * 512 + k], &g_dwT2[l][n * 512 + 256 + k], v);
    }
}

__global__ void prep_bias1(const float* __restrict__ bvl, const float* __restrict__ wvg) {
    int c = blockIdx.x, l = blockIdx.y, n = threadIdx.x;
    float acc = 0.f;
#pragma unroll
    for (int i = 0; i < 16; i++) {
        int j = c * 16 + i;
        acc += bvl[l * 256 + j] *
               (wvg[(l * 256 + j) * 512 + n] - wvg[(l * 256 + j) * 512 + 256 + n]);
    }
    g_bp[l][c][n] = acc;
}

__global__ void prep_bias2(const float* __restrict__ bq, const float* __restrict__ bk,
                           const float* __restrict__ bvg) {
    int l = blockIdx.x, t = threadIdx.x;  // 768 threads
    if (t < 256) {
        g_bcat[l][t] = bq[l * 256 + t];
    } else if (t < 512) {
        float s = bk[l * 256 + (t - 256)];
        g_bcat[l][t] = (t - 256 < 128) ? s : -s;
    } else {
        int n = t - 512;
        float acc = bvg[l * 512 + n] - bvg[l * 512 + 256 + n];
#pragma unroll
        for (int c = 0; c < 16; c++) acc += g_bp[l][c][n];
        g_bcat[l][t] = acc;
    }
}

// ===================== LN / reductions =======================================
__device__ __forceinline__ float blockSum256(float v) {
    __shared__ float sb[8];
    unsigned lane = threadIdx.x & 31, w = threadIdx.x >> 5;
#pragma unroll
    for (int o = 16; o; o >>= 1) v += __shfl_down_sync(0xffffffffu, v, o);
    if (lane == 0) sb[w] = v;
    __syncthreads();
    float r = sb[0] + sb[1] + sb[2] + sb[3] + sb[4] + sb[5] + sb[6] + sb[7];
    __syncthreads();
    return r;
}

__global__ void ln_relu_kernel(const float* __restrict__ lng, const float* __restrict__ lnb,
                               const float* __restrict__ fcb) {
    int row = blockIdx.x, d = threadIdx.x;
    size_t idx = (size_t)row * 256 + d;
    float v = g_part[0][idx] + g_part[1][idx] + g_part[2][idx] + g_part[3][idx] + fcb[d];
    float m = blockSum256(v) * (1.f / 256.f);
    float dv = v - m;
    float var = blockSum256(dv * dv) * (1.f / 256.f);
    float y = dv * rsqrtf(var + 1e-5f) * lng[d] + lnb[d];
    y = fmaxf(y, 0.f);
    split_store(&g_xs[row * 512 + d], &g_xs[row * 512 + 256 + d], y);
}

__global__ void residual_ln_kernel(const float* __restrict__ lng, const float* __restrict__ lnb,
                                   float* __restrict__ out, int writeOut) {
    int row = blockIdx.x, d = threadIdx.x;
    size_t idx = (size_t)row * 256 + d;
    float s = 0.f;
#pragma unroll
    for (int z = 0; z < 8; z++) s += g_part[z][idx];
    float xprev = __half2float(g_xs[row * 512 + d]) +
                  __half2float(g_xs[row * 512 + 256 + d]);
    float v = 0.25f * s + 0.25f * g_c[d] + 0.5f * xprev;
    float m = blockSum256(v) * (1.f / 256.f);
    float dv = v - m;
    float var = blockSum256(dv * dv) * (1.f / 256.f);
    float y = dv * rsqrtf(var + 1e-5f) * lng[d] + lnb[d];
    split_store(&g_xs[row * 512 + d], &g_xs[row * 512 + 256 + d], y);
    if (writeOut) out[idx] = y;
}

__global__ void colsum_x() {
    int b = blockIdx.x, d = threadIdx.x;
    const __half* p = g_xs + (size_t)b * 64 * 512;
    float s = 0.f;
#pragma unroll 8
    for (int r = 0; r < 64; r++)
        s += __half2float(p[r * 512 + d]) + __half2float(p[r * 512 + 256 + d]);
    g_cs[b * 256 + d] = s;
}

__global__ void cvec2(const float* __restrict__ wvl, const float* __restrict__ bvl,
                      const float* __restrict__ wvg, const float* __restrict__ bvg, int l) {
    __shared__ float s[256], t[256];
    int j = threadIdx.x;
    float a = 0.f;
    for (int b = 0; b < 64; b++) a += g_cs[b * 256 + j];
    s[j] = a;
    __syncthreads();
    float tj = 0.f;
    for (int k = 0; k < 256; k++) tj += s[k] * wvl[(l * 256 + k) * 256 + j];
    t[j] = tj + 4096.f * bvl[l * 256 + j];
    __syncthreads();
    float c = 4096.f * bvg[l * 512 + 256 + j];
    for (int k = 0; k < 256; k++) c += t[k] * wvg[(l * 256 + k) * 512 + 256 + j];
    g_c[j] = c;
}

// ===================== launch ================================================
extern "C" void kernel_launch(void* const* d_in, const int* in_sizes, int n_in,
                              void* d_out, int out_size) {
    const float* x   = (const float*)d_in[0];
    const float* fcw = (const float*)d_in[1];
    const float* fcb = (const float*)d_in[2];
    const float* lng = (const float*)d_in[3];
    const float* lnb = (const float*)d_in[4];
    const float* wq  = (const float*)d_in[5];
    const float* bq  = (const float*)d_in[6];
    const float* wk  = (const float*)d_in[7];
    const float* bk  = (const float*)d_in[8];
    const float* wvl = (const float*)d_in[9];
    const float* bvl = (const float*)d_in[10];
    const float* wvg = (const float*)d_in[11];
    const float* bvg = (const float*)d_in[12];
    float* out = (float*)d_out;

    static int attr_set = 0;
    if (!attr_set) {
        cudaFuncSetAttribute(tc_gemm, cudaFuncAttributeMaxDynamicSharedMemorySize, SMEM_DYN);
        cudaFuncSetAttribute(tc_gemm, cudaFuncAttributePreferredSharedMemoryCarveout, 100);
        attr_set = 1;
    }

    __half *pXin, *pFcw, *pWc, *pWvl, *pDw, *pXs, *pQk, *pDt, *pW;
    float *pBc, *pPart;
    cudaGetSymbolAddress((void**)&pXin, g_xin2);
    cudaGetSymbolAddress((void**)&pFcw, g_fcwT2);
    cudaGetSymbolAddress((void**)&pWc,  g_wcatT2);
    cudaGetSymbolAddress((void**)&pWvl, g_wvl2);
    cudaGetSymbolAddress((void**)&pDw,  g_dwT2);
    cudaGetSymbolAddress((void**)&pXs,  g_xs);
    cudaGetSymbolAddress((void**)&pQk,  g_qk);
    cudaGetSymbolAddress((void**)&pDt,  g_Dt);
    cudaGetSymbolAddress((void**)&pW,   g_W);
    cudaGetSymbolAddress((void**)&pBc,  g_bcat);
    cudaGetSymbolAddress((void**)&pPart, g_part);

    const float inv_sqrt_dk = 0.08838834764831845f;  // 1/sqrt(128)
    const float half_scale = 0.5f * inv_sqrt_dk;     // sigmoid via tanh

    prep_main<<<6400, 256>>>(x, fcw, wq, wk, wvl, wvg);   // 0
    prep_bias1<<<dim3(16, 2), 256>>>(bvl, wvg);           // 1
    prep_bias2<<<2, 768>>>(bq, bk, bvg);                  // 2

    // 3 (ncu capture slot): G0 partials = x @ fcw (2-term, K'=1024, split-K x4)
    tc_gemm<<<dim3(32, 4, 4), 256, SMEM_DYN>>>(
        pXin, 1024, 0, 512, 0, pFcw, 1024, 0, 0, 0,
        512, 256, nullptr, pPart, 256, nullptr, 0, 4, 0, 1.f);

    // wcomb: wcat rows 512.. = dw^T x wvl^T (3-term), fp16 store
    for (int l = 0; l < 2; l++)
        tc_gemm<<<dim3(2, 4, 1), 256, SMEM_DYN>>>(
            pDw + (size_t)l * 256 * 512, 512, 0, 256, 0,
            pWvl + (size_t)l * 256 * 512, 512, 0, 0, 256,
            256, 768, nullptr, nullptr, 0,
            pWc + (size_t)l * 768 * 512 + 512 * 512, 512, 1, 0, 1.f);

    ln_relu_kernel<<<4096, 256>>>(lng, lnb, fcb);

    for (int l = 0; l < 2; l++) {
        colsum_x<<<64, 256>>>();
        cvec2<<<1, 256>>>(wvl, bvl, wvg, bvg, l);

        // G1: [q|k'|D] = x @ wcat + bcat (2-term, K'=512). N=768 in 12 tiles:
        //     y<8 -> qk fp16 store; y>=8 -> transposed fp16 into Dt.
        tc_gemm<<<dim3(32, 12, 1), 256, SMEM_DYN>>>(
            pXs, 512, 0, 256, 0, pWc + (size_t)l * 768 * 512, 512, 0, 0, 0,
            256, 512, pBc + l * 768, (float*)pDt, 8192, pQk, 1536, 5, 512, 1.f);

        // G2: W = sigmoid(scale * qh @ kh^T) (1-term, K'=256), tanh epilogue
        tc_gemm<<<dim3(32, 64, 1), 256, SMEM_DYN>>>(
            pQk, 1536, 0, 0, 0, pQk, 1536, 256, 256, 256,
            256, 256, nullptr, nullptr, 0, pW, 4096, 2, 0, half_scale);

        // G4: partials of W @ D (single x single, K'=4096, split-K x8)
        tc_gemm<<<dim3(32, 4, 8), 256, SMEM_DYN>>>(
            pW, 4096, 0, 0, 0, pDt, 8192, 0, 0, 0,
            4096, 512, nullptr, pPart, 256, nullptr, 0, 4, 0, 1.f);

        residual_ln_kernel<<<4096, 256>>>(lng + (l + 1) * 256, lnb + (l + 1) * 256,
                                          out, (l == 1) ? 1 : 0);
    }
}

// round 13
// speedup vs baseline: 1.0764x; 1.0764x over previous
#include <cuda_runtime.h>
#include <cuda_fp16.h>
#include <cstdint>

#define NT 4096

// ===================== device scratch (no allocs) ============================
__device__ __half g_xin2[NT * 1024];         // x input split: hi 0..511 | lo 512..1023
__device__ __half g_fcwT2[256 * 1024];       // fc_w^T split
__device__ __half g_wcatT2[2][768 * 512];    // rows: [wq(256)|wk'(256)|wcomb(256)], split cols
__device__ __half g_wvl2[2][256 * 512];      // wvl rows split (for wcomb prep GEMM)
__device__ __half g_dwT2[2][256 * 512];      // (wvg0-wvg1)^T split
__device__ float g_bcat[2][768];             // [bq | bk' | bcomb]
__device__ float g_bp[2][16][256];           // bcomb partials
__device__ __half g_xs[NT * 512];            // current x split: hi 0..255 | lo 256..511
__device__ __half g_qk[NT * 1536];           // [qh kh (unused) | lo region dead]
__device__ __half g_Dt[256 * 8192];          // D^T: hi 0..4095 (lo region dead)
__device__ __half g_W[(size_t)NT * 4096];    // sigmoid W, single fp16
__device__ float g_part[8][NT * 256];        // split-K partials
__device__ float g_cs[64 * 256];
__device__ float g_c[256];

// ===================== helpers ===============================================
__device__ __forceinline__ uint32_t s2u(const void* p) {
    uint32_t a;
    asm("{ .reg .u64 t; cvta.to.shared.u64 t, %1; cvt.u32.u64 %0, t; }"
        : "=r"(a) : "l"(p));
    return a;
}

#define CP_ASYNC16(saddr, gaddr) \
    asm volatile("cp.async.cg.shared.global [%0], [%1], 16;" \
                 :: "r"(saddr), "l"(gaddr) : "memory")
#define CP_COMMIT() asm volatile("cp.async.commit_group;" ::: "memory")
#define CP_WAIT0() asm volatile("cp.async.wait_group 0;" ::: "memory")

#define LDSM_X4(r0, r1, r2, r3, addr) \
    asm volatile("ldmatrix.sync.aligned.m8n8.x4.shared.b16 {%0,%1,%2,%3}, [%4];" \
                 : "=r"(r0), "=r"(r1), "=r"(r2), "=r"(r3) : "r"(addr))

#define MMA16816(d, a, b) \
    asm volatile("mma.sync.aligned.m16n8k16.row.col.f32.f16.f16.f32 " \
                 "{%0,%1,%2,%3}, {%4,%5,%6,%7}, {%8,%9}, {%0,%1,%2,%3};" \
                 : "+f"((d)[0]), "+f"((d)[1]), "+f"((d)[2]), "+f"((d)[3]) \
                 : "r"((a)[0]), "r"((a)[1]), "r"((a)[2]), "r"((a)[3]), \
                   "r"((b)[0]), "r"((b)[1]))

// ===================== fast sigmoid via tanh.approx ==========================
__device__ __forceinline__ float sigmoid_tanh(float s_halfscaled) {
    float t;
    asm("tanh.approx.f32 %0, %1;" : "=f"(t) : "f"(s_halfscaled));
    return fmaf(0.5f, t, 0.5f);
}

// ===================== generic HMMA fp16 split GEMM ==========================
// Tile 128x128, pair-stage mainloop: 2x(BK=32) stages per barrier, 4-buffer
// ring (80B padded rows), 8 warps 2x4, warp tile 64x32, 2 CTAs/SM.
// B fragments loaded with paired ldmatrix.x4 (bitwise-identical data to x2 pairs).
// kcount must be a multiple of 64.
// modes: 0 raw fp32(+bias) -> Cf; 1 (bias?)+fp16 -> Cb; 2 sigmoid fp16 -> Cb;
// 4 fp32 partial -> Cf + z*4096*256; 5 combo: n0<nSplit mode1 else transposed.
#define ROWB 80                  // 32 fp16 = 64B data + 16B pad
#define TILEB (128 * ROWB)       // 10240
#define STAGEB (2 * TILEB)       // 20480
#define SMEM_DYN (4 * STAGEB)    // 81920

__global__ __launch_bounds__(256, 2)
void tc_gemm(const __half* __restrict__ A, int lda, int aO0, int aO1, int aO2,
             const __half* __restrict__ B, int ldb, int bO0, int bO1, int bO2,
             int Kreg, int kcount, const float* __restrict__ bias,
             float* __restrict__ Cf, int ldc,
             __half* __restrict__ Cb, int ldcb,
             int mode, int nSplit, float scale) {
    extern __shared__ __align__(16) char dsm[];
    const int tid = threadIdx.x;
    const int wid = tid >> 5, lane = tid & 31;
    const int wm = wid & 1, wn = wid >> 1;          // 2 x 4 warp grid
    const int m0 = blockIdx.x * 128, n0 = blockIdx.y * 128;
    const int kbase = blockIdx.z * kcount;
    const int P = kcount >> 6;                      // pairs of 32-K stages
    const int aO[3] = {aO0, aO1, aO2};
    const int bO[3] = {bO0, bO1, bO2};

    const uint32_t sbase = s2u(dsm);
    const int lrow = tid & 127;
    const int lc0 = tid >> 7;  // 0 or 1

    auto load_stage = [&](int buf, int kglob) {
        int region = kglob / Kreg;
        int off = kglob - region * Kreg;
        const __half* Ap = A + (size_t)(m0 + lrow) * lda + aO[region] + off;
        const __half* Bp = B + (size_t)(n0 + lrow) * ldb + bO[region] + off;
        uint32_t sa = sbase + buf * STAGEB + lrow * ROWB;
        uint32_t sb = sa + TILEB;
#pragma unroll
        for (int p = 0; p < 2; p++) {
            int ch = lc0 + 2 * p;  // 0..3
            CP_ASYNC16(sa + ch * 16, (const char*)(Ap + ch * 8));
            CP_ASYNC16(sb + ch * 16, (const char*)(Bp + ch * 8));
        }
    };

    float acc[4][4][4];
#pragma unroll
    for (int i = 0; i < 4; i++)
#pragma unroll
        for (int j = 0; j < 4; j++)
#pragma unroll
            for (int e = 0; e < 4; e++) acc[i][j][e] = 0.f;

    // preload pair 0 (buffers 0,1)
    load_stage(0, kbase);
    load_stage(1, kbase + 32);
    CP_COMMIT();

    // A frag: per mt (16 rows): lanes 0-15 rows, lanes 16-31 k+8 half
    const uint32_t a_frag_off = (wm * 64 + (lane & 15)) * ROWB + (lane >> 4) * 16;
    // B frag paired x4 over (nt_lo, nt_hi): lanes 0-7 nt_lo k0, 8-15 nt_lo k8,
    // 16-23 nt_hi k0, 24-31 nt_hi k8
    const uint32_t b_frag_off =
        (wn * 32 + ((lane >> 4) << 3) + (lane & 7)) * ROWB + ((lane >> 3) & 1) * 16;

    for (int p = 0; p < P; p++) {
        CP_WAIT0();            // pair p resident
        __syncthreads();       // all warps done with previous pair's buffers
        if (p + 1 < P) {       // prefetch pair p+1 into the other buffer pair
            int nb = ((p + 1) & 1) * 2;
            load_stage(nb, kbase + (p + 1) * 64);
            load_stage(nb + 1, kbase + (p + 1) * 64 + 32);
            CP_COMMIT();
        }
        const int pb = (p & 1) * 2;
#pragma unroll
        for (int j = 0; j < 2; j++) {
            const uint32_t sa = sbase + (pb + j) * STAGEB;
            const uint32_t sb = sa + TILEB;
#pragma unroll
            for (int kk = 0; kk < 2; kk++) {
                uint32_t af[4][4], bf[4][2];
                LDSM_X4(bf[0][0], bf[0][1], bf[1][0], bf[1][1],
                        sb + b_frag_off + kk * 32);
                LDSM_X4(bf[2][0], bf[2][1], bf[3][0], bf[3][1],
                        sb + b_frag_off + 16 * ROWB + kk * 32);
#pragma unroll
                for (int mt = 0; mt < 4; mt++)
                    LDSM_X4(af[mt][0], af[mt][1], af[mt][2], af[mt][3],
                            sa + a_frag_off + mt * (16 * ROWB) + kk * 32);
#pragma unroll
                for (int mt = 0; mt < 4; mt++)
#pragma unroll
                    for (int nt = 0; nt < 4; nt++)
                        MMA16816(acc[mt][nt], af[mt], bf[nt]);
            }
        }
    }

    // ---- epilogue ----
    const int tr = lane >> 2, tc = lane & 3;
    const int mbase = m0 + wm * 64 + tr;
    const int nbase = n0 + wn * 32 + tc * 2;

    int emode = mode;
    if (mode == 5) emode = (n0 >= nSplit) ? 3 : 1;

    if (emode == 0 || emode == 4) {
        float* base = Cf + (emode == 4 ? (size_t)blockIdx.z * (4096 * 256) : 0);
#pragma unroll
        for (int mt = 0; mt < 4; mt++)
#pragma unroll
            for (int h = 0; h < 2; h++) {
                int m = mbase + mt * 16 + h * 8;
                float* rowp = base + (size_t)m * ldc;
#pragma unroll
                for (int nt = 0; nt < 4; nt++) {
                    int n = nbase + nt * 8;
                    float v0 = acc[mt][nt][2 * h + 0];
                    float v1 = acc[mt][nt][2 * h + 1];
                    if (bias) { v0 += bias[n]; v1 += bias[n + 1]; }
                    *(float2*)(rowp + n) = make_float2(v0, v1);
                }
            }
    } else if (emode == 1) {
#pragma unroll
        for (int mt = 0; mt < 4; mt++)
#pragma unroll
            for (int h = 0; h < 2; h++) {
                int m = mbase + mt * 16 + h * 8;
                __half* rowp = Cb + (size_t)m * ldcb;
#pragma unroll
                for (int nt = 0; nt < 4; nt++) {
                    int n = nbase + nt * 8;
                    float v0 = acc[mt][nt][2 * h + 0];
                    float v1 = acc[mt][nt][2 * h + 1];
                    if (bias) { v0 += bias[n]; v1 += bias[n + 1]; }
                    *(__half2*)(rowp + n) =
                        __halves2half2(__float2half_rn(v0), __float2half_rn(v1));
                }
            }
    } else if (emode == 2) {
#pragma unroll
        for (int mt = 0; mt < 4; mt++)
#pragma unroll
            for (int h = 0; h < 2; h++) {
                int m = mbase + mt * 16 + h * 8;
                __half* rowp = Cb + (size_t)m * ldcb;
#pragma unroll
                for (int nt = 0; nt < 4; nt++) {
                    int n = nbase + nt * 8;
                    float v0 = sigmoid_tanh(scale * acc[mt][nt][2 * h + 0]);
                    float v1 = sigmoid_tanh(scale * acc[mt][nt][2 * h + 1]);
                    *(__half2*)(rowp + n) =
                        __halves2half2(__float2half_rn(v0), __float2half_rn(v1));
                }
            }
    } else {  // emode 3: transposed fp16 into (half*)Cf, ld=ldc
        __half* Ct = (__half*)Cf;
#pragma unroll
        for (int mt = 0; mt < 4; mt++)
#pragma unroll
            for (int h = 0; h < 2; h++) {
                int m = mbase + mt * 16 + h * 8;
#pragma unroll
                for (int nt = 0; nt < 4; nt++) {
                    int n = nbase + nt * 8;
#pragma unroll
                    for (int e = 0; e < 2; e++) {
                        float v = acc[mt][nt][2 * h + e] + bias[n + e];
                        Ct[(size_t)(n + e - nSplit) * ldc + m] = __float2half_rn(v);
                    }
                }
            }
    }
}

// ===================== prep kernels ==========================================
__device__ __forceinline__ void split_store(__half* hi, __half* lo, float v) {
    __half h = __float2half_rn(v);
    *hi = h;
    *lo = __float2half_rn(v - __half2float(h));
}

// Segmented prep kernel. blocks: [0,4096) x | [4096,4352) fcw | [4352,5376)
// wcat | [5376,5888) wvl | [5888,6400) dw
__global__ void prep_main(const float* __restrict__ x, const float* __restrict__ fcw,
                          const float* __restrict__ wq, const float* __restrict__ wk,
                          const float* __restrict__ wvl, const float* __restrict__ wvg) {
    int b = blockIdx.x, t = threadIdx.x;
    if (b < 4096) {
        int row = b;
#pragma unroll
        for (int i = 0; i < 2; i++) {
            int c = t + i * 256;
            split_store(&g_xin2[row * 1024 + c], &g_xin2[row * 1024 + 512 + c],
                        x[row * 512 + c]);
        }
    } else if (b < 4352) {
        int n = b - 4096;
#pragma unroll
        for (int i = 0; i < 2; i++) {
            int k = t + i * 256;
            split_store(&g_fcwT2[n * 1024 + k], &g_fcwT2[n * 1024 + 512 + k],
                        fcw[k * 256 + n]);
        }
    } else if (b < 5376) {
        int idx = b - 4352, l = idx >> 9, n = idx & 511, k = t;
        float v;
        if (n < 256) v = wq[(l * 256 + k) * 256 + n];
        else {
            float s = wk[(l * 256 + k) * 256 + (n - 256)];
            v = (n - 256 < 128) ? s : -s;
        }
        split_store(&g_wcatT2[l][n * 512 + k], &g_wcatT2[l][n * 512 + 256 + k], v);
    } else if (b < 5888) {
        int idx = b - 5376, l = idx >> 8, k = idx & 255, j = t;
        float v = wvl[(l * 256 + k) * 256 + j];
        split_store(&g_wvl2[l][k * 512 + j], &g_wvl2[l][k * 512 + 256 + j], v);
    } else {
        int idx = b - 5888, l = idx >> 8, n = idx & 255, k = t;
        float v = wvg[(l * 256 + k) * 512 + n] - wvg[(l * 256 + k) * 512 + 256 + n];
        split_store(&g_dwT2[l][n * 512 + k], &g_dwT2[l][n * 512 + 256 + k], v);
    }
}

__global__ void prep_bias1(const float* __restrict__ bvl, const float* __restrict__ wvg) {
    int c = blockIdx.x, l = blockIdx.y, n = threadIdx.x;
    float acc = 0.f;
#pragma unroll
    for (int i = 0; i < 16; i++) {
        int j = c * 16 + i;
        acc += bvl[l * 256 + j] *
               (wvg[(l * 256 + j) * 512 + n] - wvg[(l * 256 + j) * 512 + 256 + n]);
    }
    g_bp[l][c][n] = acc;
}

__global__ void prep_bias2(const float* __restrict__ bq, const float* __restrict__ bk,
                           const float* __restrict__ bvg) {
    int l = blockIdx.x, t = threadIdx.x;  // 768 threads
    if (t < 256) {
        g_bcat[l][t] = bq[l * 256 + t];
    } else if (t < 512) {
        float s = bk[l * 256 + (t - 256)];
        g_bcat[l][t] = (t - 256 < 128) ? s : -s;
    } else {
        int n = t - 512;
        float acc = bvg[l * 512 + n] - bvg[l * 512 + 256 + n];
#pragma unroll
        for (int c = 0; c < 16; c++) acc += g_bp[l][c][n];
        g_bcat[l][t] = acc;
    }
}

// ===================== LN / reductions =======================================
__device__ __forceinline__ float blockSum256(float v) {
    __shared__ float sb[8];
    unsigned lane = threadIdx.x & 31, w = threadIdx.x >> 5;
#pragma unroll
    for (int o = 16; o; o >>= 1) v += __shfl_down_sync(0xffffffffu, v, o);
    if (lane == 0) sb[w] = v;
    __syncthreads();
    float r = sb[0] + sb[1] + sb[2] + sb[3] + sb[4] + sb[5] + sb[6] + sb[7];
    __syncthreads();
    return r;
}

__global__ void ln_relu_kernel(const float* __restrict__ lng, const float* __restrict__ lnb,
                               const float* __restrict__ fcb) {
    int row = blockIdx.x, d = threadIdx.x;
    size_t idx = (size_t)row * 256 + d;
    float v = g_part[0][idx] + g_part[1][idx] + g_part[2][idx] + g_part[3][idx] + fcb[d];
    float m = blockSum256(v) * (1.f / 256.f);
    float dv = v - m;
    float var = blockSum256(dv * dv) * (1.f / 256.f);
    float y = dv * rsqrtf(var + 1e-5f) * lng[d] + lnb[d];
    y = fmaxf(y, 0.f);
    split_store(&g_xs[row * 512 + d], &g_xs[row * 512 + 256 + d], y);
}

__global__ void residual_ln_kernel(const float* __restrict__ lng, const float* __restrict__ lnb,
                                   float* __restrict__ out, int writeOut) {
    int row = blockIdx.x, d = threadIdx.x;
    size_t idx = (size_t)row * 256 + d;
    float s = 0.f;
#pragma unroll
    for (int z = 0; z < 8; z++) s += g_part[z][idx];
    float xprev = __half2float(g_xs[row * 512 + d]) +
                  __half2float(g_xs[row * 512 + 256 + d]);
    float v = 0.25f * s + 0.25f * g_c[d] + 0.5f * xprev;
    float m = blockSum256(v) * (1.f / 256.f);
    float dv = v - m;
    float var = blockSum256(dv * dv) * (1.f / 256.f);
    float y = dv * rsqrtf(var + 1e-5f) * lng[d] + lnb[d];
    split_store(&g_xs[row * 512 + d], &g_xs[row * 512 + 256 + d], y);
    if (writeOut) out[idx] = y;
}

__global__ void colsum_x() {
    int b = blockIdx.x, d = threadIdx.x;
    const __half* p = g_xs + (size_t)b * 64 * 512;
    float s = 0.f;
#pragma unroll 8
    for (int r = 0; r < 64; r++)
        s += __half2float(p[r * 512 + d]) + __half2float(p[r * 512 + 256 + d]);
    g_cs[b * 256 + d] = s;
}

__global__ void cvec2(const float* __restrict__ wvl, const float* __restrict__ bvl,
                      const float* __restrict__ wvg, const float* __restrict__ bvg, int l) {
    __shared__ float s[256], t[256];
    int j = threadIdx.x;
    float a = 0.f;
    for (int b = 0; b < 64; b++) a += g_cs[b * 256 + j];
    s[j] = a;
    __syncthreads();
    float tj = 0.f;
    for (int k = 0; k < 256; k++) tj += s[k] * wvl[(l * 256 + k) * 256 + j];
    t[j] = tj + 4096.f * bvl[l * 256 + j];
    __syncthreads();
    float c = 4096.f * bvg[l * 512 + 256 + j];
    for (int k = 0; k < 256; k++) c += t[k] * wvg[(l * 256 + k) * 512 + 256 + j];
    g_c[j] = c;
}

// ===================== launch ================================================
extern "C" void kernel_launch(void* const* d_in, const int* in_sizes, int n_in,
                              void* d_out, int out_size) {
    const float* x   = (const float*)d_in[0];
    const float* fcw = (const float*)d_in[1];
    const float* fcb = (const float*)d_in[2];
    const float* lng = (const float*)d_in[3];
    const float* lnb = (const float*)d_in[4];
    const float* wq  = (const float*)d_in[5];
    const float* bq  = (const float*)d_in[6];
    const float* wk  = (const float*)d_in[7];
    const float* bk  = (const float*)d_in[8];
    const float* wvl = (const float*)d_in[9];
    const float* bvl = (const float*)d_in[10];
    const float* wvg = (const float*)d_in[11];
    const float* bvg = (const float*)d_in[12];
    float* out = (float*)d_out;

    static int attr_set = 0;
    if (!attr_set) {
        cudaFuncSetAttribute(tc_gemm, cudaFuncAttributeMaxDynamicSharedMemorySize, SMEM_DYN);
        cudaFuncSetAttribute(tc_gemm, cudaFuncAttributePreferredSharedMemoryCarveout, 100);
        attr_set = 1;
    }

    __half *pXin, *pFcw, *pWc, *pWvl, *pDw, *pXs, *pQk, *pDt, *pW;
    float *pBc, *pPart;
    cudaGetSymbolAddress((void**)&pXin, g_xin2);
    cudaGetSymbolAddress((void**)&pFcw, g_fcwT2);
    cudaGetSymbolAddress((void**)&pWc,  g_wcatT2);
    cudaGetSymbolAddress((void**)&pWvl, g_wvl2);
    cudaGetSymbolAddress((void**)&pDw,  g_dwT2);
    cudaGetSymbolAddress((void**)&pXs,  g_xs);
    cudaGetSymbolAddress((void**)&pQk,  g_qk);
    cudaGetSymbolAddress((void**)&pDt,  g_Dt);
    cudaGetSymbolAddress((void**)&pW,   g_W);
    cudaGetSymbolAddress((void**)&pBc,  g_bcat);
    cudaGetSymbolAddress((void**)&pPart, g_part);

    const float inv_sqrt_dk = 0.08838834764831845f;  // 1/sqrt(128)
    const float half_scale = 0.5f * inv_sqrt_dk;     // sigmoid via tanh

    prep_main<<<6400, 256>>>(x, fcw, wq, wk, wvl, wvg);   // 0
    prep_bias1<<<dim3(16, 2), 256>>>(bvl, wvg);           // 1
    prep_bias2<<<2, 768>>>(bq, bk, bvg);                  // 2

    // 3 (ncu capture slot): G0 partials = x @ fcw (2-term, K'=1024, split-K x4)
    tc_gemm<<<dim3(32, 2, 4), 256, SMEM_DYN>>>(
        pXin, 1024, 0, 512, 0, pFcw, 1024, 0, 0, 0,
        512, 256, nullptr, pPart, 256, nullptr, 0, 4, 0, 1.f);

    // wcomb: wcat rows 512.. = dw^T x wvl^T (3-term), fp16 store
    for (int l = 0; l < 2; l++)
        tc_gemm<<<dim3(2, 2, 1), 256, SMEM_DYN>>>(
            pDw + (size_t)l * 256 * 512, 512, 0, 256, 0,
            pWvl + (size_t)l * 256 * 512, 512, 0, 0, 256,
            256, 768, nullptr, nullptr, 0,
            pWc + (size_t)l * 768 * 512 + 512 * 512, 512, 1, 0, 1.f);

    ln_relu_kernel<<<4096, 256>>>(lng, lnb, fcb);

    for (int l = 0; l < 2; l++) {
        colsum_x<<<64, 256>>>();
        cvec2<<<1, 256>>>(wvl, bvl, wvg, bvg, l);

        // G1: [q|k'|D] = x @ wcat + bcat (2-term, K'=512).
        tc_gemm<<<dim3(32, 6, 1), 256, SMEM_DYN>>>(
            pXs, 512, 0, 256, 0, pWc + (size_t)l * 768 * 512, 512, 0, 0, 0,
            256, 512, pBc + l * 768, (float*)pDt, 8192, pQk, 1536, 5, 512, 1.f);

        // G2: W = sigmoid(scale * qh @ kh^T) (1-term, K'=256), tanh epilogue
        tc_gemm<<<dim3(32, 32, 1), 256, SMEM_DYN>>>(
            pQk, 1536, 0, 0, 0, pQk, 1536, 256, 256, 256,
            256, 256, nullptr, nullptr, 0, pW, 4096, 2, 0, half_scale);

        // G4: partials of W @ D (single x single, K'=4096, split-K x8)
        tc_gemm<<<dim3(32, 2, 8), 256, SMEM_DYN>>>(
            pW, 4096, 0, 0, 0, pDt, 8192, 0, 0, 0,
            4096, 512, nullptr, pPart, 256, nullptr, 0, 4, 0, 1.f);

        residual_ln_kernel<<<4096, 256>>>(lng + (l + 1) * 256, lnb + (l + 1) * 256,
                                          out, (l == 1) ? 1 : 0);
    }
}

// round 15
// speedup vs baseline: 1.1014x; 1.0233x over previous
#include <cuda_runtime.h>
#include <cuda_fp16.h>
#include <cstdint>

#define NT 4096

// ===================== device scratch (no allocs) ============================
__device__ __half g_xin2[NT * 1024];         // x input split: hi 0..511 | lo 512..1023
__device__ __half g_fcwT2[256 * 1024];       // fc_w^T split
__device__ __half g_wcatT2[2][768 * 512];    // rows: [wq(256)|wk'(256)|wcomb(256)], split cols
__device__ __half g_wvl2[2][256 * 512];      // wvl rows split (for wcomb prep GEMM)
__device__ __half g_dwT2[2][256 * 512];      // (wvg0-wvg1)^T split
__device__ float g_bcat[2][768];             // [bq | bk' | bcomb]
__device__ float g_bp[2][16][256];           // bcomb partials
__device__ __half g_xs[NT * 512];            // current x split: hi 0..255 | lo 256..511
__device__ __half g_qk[NT * 1536];           // [qh kh (unused) | lo region dead]
__device__ __half g_Dt[256 * 8192];          // D^T: hi 0..4095 (lo region dead)
__device__ __half g_W[(size_t)NT * 4096];    // sigmoid W, single fp16
__device__ float g_part[8][NT * 256];        // split-K partials
__device__ float g_cs[64 * 256];
__device__ float g_c[256];

// ===================== helpers ===============================================
__device__ __forceinline__ uint32_t s2u(const void* p) {
    uint32_t a;
    asm("{ .reg .u64 t; cvta.to.shared.u64 t, %1; cvt.u32.u64 %0, t; }"
        : "=r"(a) : "l"(p));
    return a;
}

#define CP_ASYNC16(saddr, gaddr) \
    asm volatile("cp.async.cg.shared.global [%0], [%1], 16;" \
                 :: "r"(saddr), "l"(gaddr) : "memory")
#define CP_COMMIT() asm volatile("cp.async.commit_group;" ::: "memory")
#define CP_WAIT1() asm volatile("cp.async.wait_group 1;" ::: "memory")

#define LDSM_X4(r0, r1, r2, r3, addr) \
    asm volatile("ldmatrix.sync.aligned.m8n8.x4.shared.b16 {%0,%1,%2,%3}, [%4];" \
                 : "=r"(r0), "=r"(r1), "=r"(r2), "=r"(r3) : "r"(addr))

#define MMA16816(d, a, b) \
    asm volatile("mma.sync.aligned.m16n8k16.row.col.f32.f16.f16.f32 " \
                 "{%0,%1,%2,%3}, {%4,%5,%6,%7}, {%8,%9}, {%0,%1,%2,%3};" \
                 : "+f"((d)[0]), "+f"((d)[1]), "+f"((d)[2]), "+f"((d)[3]) \
                 : "r"((a)[0]), "r"((a)[1]), "r"((a)[2]), "r"((a)[3]), \
                   "r"((b)[0]), "r"((b)[1]))

// ===================== fast sigmoid via tanh.approx ==========================
__device__ __forceinline__ float sigmoid_tanh(float s_halfscaled) {
    float t;
    asm("tanh.approx.f32 %0, %1;" : "=f"(t) : "f"(s_halfscaled));
    return fmaf(0.5f, t, 0.5f);
}

// ===================== generic HMMA fp16 split GEMM ==========================
// Tile 128x128, pair-stage mainloop (2x BK=32 per barrier), SIX-stage ring,
// 64B rows with XOR chunk swizzle (chunk c at c ^ ((row>>1)&3)) ->
// conflict-free ldmatrix, 16B-aligned cp.async. Depth-2 pair prefetch.
// 8 warps 2x4, warp tile 64x32, 2 CTAs/SM. kcount multiple of 64.
// modes: 0 raw fp32(+bias) -> Cf; 1 (bias?)+fp16 -> Cb; 2 sigmoid fp16 -> Cb;
// 4 fp32 partial -> Cf + z*4096*256; 5 combo: n0<nSplit mode1 else transposed.
#define TILEB (128 * 64)         // 8192
#define STAGEB (2 * TILEB)       // 16384
#define SMEM_DYN (6 * STAGEB)    // 98304

__global__ __launch_bounds__(256, 2)
void tc_gemm(const __half* __restrict__ A, int lda, int aO0, int aO1, int aO2,
             const __half* __restrict__ B, int ldb, int bO0, int bO1, int bO2,
             int Kreg, int kcount, const float* __restrict__ bias,
             float* __restrict__ Cf, int ldc,
             __half* __restrict__ Cb, int ldcb,
             int mode, int nSplit, float scale) {
    extern __shared__ __align__(16) char dsm[];
    const int tid = threadIdx.x;
    const int wid = tid >> 5, lane = tid & 31;
    const int wm = wid & 1, wn = wid >> 1;          // 2 x 4 warp grid
    const int m0 = blockIdx.x * 128, n0 = blockIdx.y * 128;
    const int kbase = blockIdx.z * kcount;
    const int P = kcount >> 6;                      // pairs of 32-K stages
    const int aO[3] = {aO0, aO1, aO2};
    const int bO[3] = {bO0, bO1, bO2};

    const uint32_t sbase = s2u(dsm);
    const int lrow = tid & 127;
    const int lc0 = tid >> 7;                       // 0 or 1
    const int lsw = (lrow >> 1) & 3;                // swizzle key for loader

    // buf in [0,6): stage buffer index
    auto load_stage = [&](int buf, int kglob) {
        int region = kglob / Kreg;
        int off = kglob - region * Kreg;
        const __half* Ap = A + (size_t)(m0 + lrow) * lda + aO[region] + off;
        const __half* Bp = B + (size_t)(n0 + lrow) * ldb + bO[region] + off;
        uint32_t sa = sbase + buf * STAGEB + lrow * 64;
        uint32_t sb = sa + TILEB;
#pragma unroll
        for (int p = 0; p < 2; p++) {
            int ch = lc0 + 2 * p;                   // 0..3
            uint32_t so = (uint32_t)((ch ^ lsw) * 16);
            CP_ASYNC16(sa + so, (const char*)(Ap + ch * 8));
            CP_ASYNC16(sb + so, (const char*)(Bp + ch * 8));
        }
    };

    float acc[4][4][4];
#pragma unroll
    for (int i = 0; i < 4; i++)
#pragma unroll
        for (int j = 0; j < 4; j++)
#pragma unroll
            for (int e = 0; e < 4; e++) acc[i][j][e] = 0.f;

    // prologue: pairs 0 and 1 (stage buffers 0..3), one commit group per pair
    load_stage(0, kbase);
    load_stage(1, kbase + 32);
    CP_COMMIT();
    if (P > 1) {
        load_stage(2, kbase + 64);
        load_stage(3, kbase + 96);
    }
    CP_COMMIT();

    // A fragment addressing (row = wm*64 + (lane&15) + mt*16; mt*16 keeps the
    // swizzle key invariant). Chunk bit0 = lane>>4, bit1 = kk.
    const int rA = wm * 64 + (lane & 15);
    const int swA = (rA >> 1) & 3;
    const uint32_t aBase = (uint32_t)rA * 64;
    const uint32_t aCk[2] = { (uint32_t)((((lane >> 4) ^ swA) & 3) * 16),
                              (uint32_t)(((((lane >> 4) ^ swA) ^ 2) & 3) * 16) };
    // B fragment addressing (rows rB and rB+16; +16 keeps key invariant).
    const int rB = wn * 32 + ((lane >> 4) << 3) + (lane & 7);
    const int swB = (rB >> 1) & 3;
    const uint32_t bBase = (uint32_t)rB * 64;
    const uint32_t bCk[2] = { (uint32_t)(((((lane >> 3) & 1) ^ swB) & 3) * 16),
                              (uint32_t)((((((lane >> 3) & 1) ^ swB) ^ 2) & 3) * 16) };

    int buf0 = 0;  // stage buffer of pair p (= (2p) % 6)
    for (int p = 0; p < P; p++) {
        CP_WAIT1();            // pair p resident (pair p+1 may still fly)
        __syncthreads();       // compute of pair p-1 done -> its buffers free
        if (p + 2 < P) {       // prefetch pair p+2 into pair (p-1)'s buffers
            int nb = buf0 + 4; if (nb >= 6) nb -= 6;
            load_stage(nb, kbase + (p + 2) * 64);
            load_stage(nb + 1, kbase + (p + 2) * 64 + 32);
        }
        CP_COMMIT();           // keep group count in lockstep with pairs
#pragma unroll
        for (int j = 0; j < 2; j++) {
            const uint32_t sa = sbase + (buf0 + j) * STAGEB;
            const uint32_t sb = sa + TILEB;
#pragma unroll
            for (int kk = 0; kk < 2; kk++) {
                uint32_t af[4][4], bf[4][2];
                LDSM_X4(bf[0][0], bf[0][1], bf[1][0], bf[1][1],
                        sb + bBase + bCk[kk]);
                LDSM_X4(bf[2][0], bf[2][1], bf[3][0], bf[3][1],
                        sb + bBase + 1024 + bCk[kk]);
#pragma unroll
                for (int mt = 0; mt < 4; mt++)
                    LDSM_X4(af[mt][0], af[mt][1], af[mt][2], af[mt][3],
                            sa + aBase + mt * 1024 + aCk[kk]);
#pragma unroll
                for (int mt = 0; mt < 4; mt++)
#pragma unroll
                    for (int nt = 0; nt < 4; nt++)
                        MMA16816(acc[mt][nt], af[mt], bf[nt]);
            }
        }
        buf0 += 2; if (buf0 >= 6) buf0 -= 6;
    }

    // ---- epilogue ----
    const int tr = lane >> 2, tc = lane & 3;
    const int mbase = m0 + wm * 64 + tr;
    const int nbase = n0 + wn * 32 + tc * 2;

    int emode = mode;
    if (mode == 5) emode = (n0 >= nSplit) ? 3 : 1;

    if (emode == 0 || emode == 4) {
        float* base = Cf + (emode == 4 ? (size_t)blockIdx.z * (4096 * 256) : 0);
#pragma unroll
        for (int mt = 0; mt < 4; mt++)
#pragma unroll
            for (int h = 0; h < 2; h++) {
                int m = mbase + mt * 16 + h * 8;
                float* rowp = base + (size_t)m * ldc;
#pragma unroll
                for (int nt = 0; nt < 4; nt++) {
                    int n = nbase + nt * 8;
                    float v0 = acc[mt][nt][2 * h + 0];
                    float v1 = acc[mt][nt][2 * h + 1];
                    if (bias) { v0 += bias[n]; v1 += bias[n + 1]; }
                    *(float2*)(rowp + n) = make_float2(v0, v1);
                }
            }
    } else if (emode == 1) {
#pragma unroll
        for (int mt = 0; mt < 4; mt++)
#pragma unroll
            for (int h = 0; h < 2; h++) {
                int m = mbase + mt * 16 + h * 8;
                __half* rowp = Cb + (size_t)m * ldcb;
#pragma unroll
                for (int nt = 0; nt < 4; nt++) {
                    int n = nbase + nt * 8;
                    float v0 = acc[mt][nt][2 * h + 0];
                    float v1 = acc[mt][nt][2 * h + 1];
                    if (bias) { v0 += bias[n]; v1 += bias[n + 1]; }
                    *(__half2*)(rowp + n) =
                        __halves2half2(__float2half_rn(v0), __float2half_rn(v1));
                }
            }
    } else if (emode == 2) {
#pragma unroll
        for (int mt = 0; mt < 4; mt++)
#pragma unroll
            for (int h = 0; h < 2; h++) {
                int m = mbase + mt * 16 + h * 8;
                __half* rowp = Cb + (size_t)m * ldcb;
#pragma unroll
                for (int nt = 0; nt < 4; nt++) {
                    int n = nbase + nt * 8;
                    float v0 = sigmoid_tanh(scale * acc[mt][nt][2 * h + 0]);
                    float v1 = sigmoid_tanh(scale * acc[mt][nt][2 * h + 1]);
                    *(__half2*)(rowp + n) =
                        __halves2half2(__float2half_rn(v0), __float2half_rn(v1));
                }
            }
    } else {  // emode 3: transposed fp16 into (half*)Cf, ld=ldc
        __half* Ct = (__half*)Cf;
#pragma unroll
        for (int mt = 0; mt < 4; mt++)
#pragma unroll
            for (int h = 0; h < 2; h++) {
                int m = mbase + mt * 16 + h * 8;
#pragma unroll
                for (int nt = 0; nt < 4; nt++) {
                    int n = nbase + nt * 8;
#pragma unroll
                    for (int e = 0; e < 2; e++) {
                        float v = acc[mt][nt][2 * h + e] + bias[n + e];
                        Ct[(size_t)(n + e - nSplit) * ldc + m] = __float2half_rn(v);
                    }
                }
            }
    }
}

// ===================== prep kernels ==========================================
__device__ __forceinline__ void split_store(__half* hi, __half* lo, float v) {
    __half h = __float2half_rn(v);
    *hi = h;
    *lo = __float2half_rn(v - __half2float(h));
}

// Segmented prep kernel. blocks: [0,4096) x | [4096,4352) fcw | [4352,5376)
// wcat | [5376,5888) wvl | [5888,6400) dw
__global__ void prep_main(const float* __restrict__ x, const float* __restrict__ fcw,
                          const float* __restrict__ wq, const float* __restrict__ wk,
                          const float* __restrict__ wvl, const float* __restrict__ wvg) {
    int b = blockIdx.x, t = threadIdx.x;
    if (b < 4096) {
        int row = b;
#pragma unroll
        for (int i = 0; i < 2; i++) {
            int c = t + i * 256;
            split_store(&g_xin2[row * 1024 + c], &g_xin2[row * 1024 + 512 + c],
                        x[row * 512 + c]);
        }
    } else if (b < 4352) {
        int n = b - 4096;
#pragma unroll
        for (int i = 0; i < 2; i++) {
            int k = t + i * 256;
            split_store(&g_fcwT2[n * 1024 + k], &g_fcwT2[n * 1024 + 512 + k],
                        fcw[k * 256 + n]);
        }
    } else if (b < 5376) {
        int idx = b - 4352, l = idx >> 9, n = idx & 511, k = t;
        float v;
        if (n < 256) v = wq[(l * 256 + k) * 256 + n];
        else {
            float s = wk[(l * 256 + k) * 256 + (n - 256)];
            v = (n - 256 < 128) ? s : -s;
        }
        split_store(&g_wcatT2[l][n * 512 + k], &g_wcatT2[l][n * 512 + 256 + k], v);
    } else if (b < 5888) {
        int idx = b - 5376, l = idx >> 8, k = idx & 255, j = t;
        float v = wvl[(l * 256 + k) * 256 + j];
        split_store(&g_wvl2[l][k * 512 + j], &g_wvl2[l][k * 512 + 256 + j], v);
    } else {
        int idx = b - 5888, l = idx >> 8, n = idx & 255, k = t;
        float v = wvg[(l * 256 + k) * 512 + n] - wvg[(l * 256 + k) * 512 + 256 + n];
        split_store(&g_dwT2[l][n * 512 + k], &g_dwT2[l][n * 512 + 256 + k], v);
    }
}

__global__ void prep_bias1(const float* __restrict__ bvl, const float* __restrict__ wvg) {
    int c = blockIdx.x, l = blockIdx.y, n = threadIdx.x;
    float acc = 0.f;
#pragma unroll
    for (int i = 0; i < 16; i++) {
        int j = c * 16 + i;
        acc += bvl[l * 256 + j] *
               (wvg[(l * 256 + j) * 512 + n] - wvg[(l * 256 + j) * 512 + 256 + n]);
    }
    g_bp[l][c][n] = acc;
}

__global__ void prep_bias2(const float* __restrict__ bq, const float* __restrict__ bk,
                           const float* __restrict__ bvg) {
    int l = blockIdx.x, t = threadIdx.x;  // 768 threads
    if (t < 256) {
        g_bcat[l][t] = bq[l * 256 + t];
    } else if (t < 512) {
        float s = bk[l * 256 + (t - 256)];
        g_bcat[l][t] = (t - 256 < 128) ? s : -s;
    } else {
        int n = t - 512;
        float acc = bvg[l * 512 + n] - bvg[l * 512 + 256 + n];
#pragma unroll
        for (int c = 0; c < 16; c++) acc += g_bp[l][c][n];
        g_bcat[l][t] = acc;
    }
}

// ===================== LN / reductions =======================================
__device__ __forceinline__ float blockSum256(float v) {
    __shared__ float sb[8];
    unsigned lane = threadIdx.x & 31, w = threadIdx.x >> 5;
#pragma unroll
    for (int o = 16; o; o >>= 1) v += __shfl_down_sync(0xffffffffu, v, o);
    if (lane == 0) sb[w] = v;
    __syncthreads();
    float r = sb[0] + sb[1] + sb[2] + sb[3] + sb[4] + sb[5] + sb[6] + sb[7];
    __syncthreads();
    return r;
}

__global__ void ln_relu_kernel(const float* __restrict__ lng, const float* __restrict__ lnb,
                               const float* __restrict__ fcb) {
    int row = blockIdx.x, d = threadIdx.x;
    size_t idx = (size_t)row * 256 + d;
    float v = g_part[0][idx] + g_part[1][idx] + g_part[2][idx] + g_part[3][idx] + fcb[d];
    float m = blockSum256(v) * (1.f / 256.f);
    float dv = v - m;
    float var = blockSum256(dv * dv) * (1.f / 256.f);
    float y = dv * rsqrtf(var + 1e-5f) * lng[d] + lnb[d];
    y = fmaxf(y, 0.f);
    split_store(&g_xs[row * 512 + d], &g_xs[row * 512 + 256 + d], y);
}

__global__ void residual_ln_kernel(const float* __restrict__ lng, const float* __restrict__ lnb,
                                   float* __restrict__ out, int writeOut) {
    int row = blockIdx.x, d = threadIdx.x;
    size_t idx = (size_t)row * 256 + d;
    float s = 0.f;
#pragma unroll
    for (int z = 0; z < 8; z++) s += g_part[z][idx];
    float xprev = __half2float(g_xs[row * 512 + d]) +
                  __half2float(g_xs[row * 512 + 256 + d]);
    float v = 0.25f * s + 0.25f * g_c[d] + 0.5f * xprev;
    float m = blockSum256(v) * (1.f / 256.f);
    float dv = v - m;
    float var = blockSum256(dv * dv) * (1.f / 256.f);
    float y = dv * rsqrtf(var + 1e-5f) * lng[d] + lnb[d];
    split_store(&g_xs[row * 512 + d], &g_xs[row * 512 + 256 + d], y);
    if (writeOut) out[idx] = y;
}

__global__ void colsum_x() {
    int b = blockIdx.x, d = threadIdx.x;
    const __half* p = g_xs + (size_t)b * 64 * 512;
    float s = 0.f;
#pragma unroll 8
    for (int r = 0; r < 64; r++)
        s += __half2float(p[r * 512 + d]) + __half2float(p[r * 512 + 256 + d]);
    g_cs[b * 256 + d] = s;
}

__global__ void cvec2(const float* __restrict__ wvl, const float* __restrict__ bvl,
                      const float* __restrict__ wvg, const float* __restrict__ bvg, int l) {
    __shared__ float s[256], t[256];
    int j = threadIdx.x;
    float a = 0.f;
    for (int b = 0; b < 64; b++) a += g_cs[b * 256 + j];
    s[j] = a;
    __syncthreads();
    float tj = 0.f;
    for (int k = 0; k < 256; k++) tj += s[k] * wvl[(l * 256 + k) * 256 + j];
    t[j] = tj + 4096.f * bvl[l * 256 + j];
    __syncthreads();
    float c = 4096.f * bvg[l * 512 + 256 + j];
    for (int k = 0; k < 256; k++) c += t[k] * wvg[(l * 256 + k) * 512 + 256 + j];
    g_c[j] = c;
}

// ===================== launch ================================================
extern "C" void kernel_launch(void* const* d_in, const int* in_sizes, int n_in,
                              void* d_out, int out_size) {
    const float* x   = (const float*)d_in[0];
    const float* fcw = (const float*)d_in[1];
    const float* fcb = (const float*)d_in[2];
    const float* lng = (const float*)d_in[3];
    const float* lnb = (const float*)d_in[4];
    const float* wq  = (const float*)d_in[5];
    const float* bq  = (const float*)d_in[6];
    const float* wk  = (const float*)d_in[7];
    const float* bk  = (const float*)d_in[8];
    const float* wvl = (const float*)d_in[9];
    const float* bvl = (const float*)d_in[10];
    const float* wvg = (const float*)d_in[11];
    const float* bvg = (const float*)d_in[12];
    float* out = (float*)d_out;

    static int attr_set = 0;
    if (!attr_set) {
        cudaFuncSetAttribute(tc_gemm, cudaFuncAttributeMaxDynamicSharedMemorySize, SMEM_DYN);
        cudaFuncSetAttribute(tc_gemm, cudaFuncAttributePreferredSharedMemoryCarveout, 100);
        attr_set = 1;
    }

    __half *pXin, *pFcw, *pWc, *pWvl, *pDw, *pXs, *pQk, *pDt, *pW;
    float *pBc, *pPart;
    cudaGetSymbolAddress((void**)&pXin, g_xin2);
    cudaGetSymbolAddress((void**)&pFcw, g_fcwT2);
    cudaGetSymbolAddress((void**)&pWc,  g_wcatT2);
    cudaGetSymbolAddress((void**)&pWvl, g_wvl2);
    cudaGetSymbolAddress((void**)&pDw,  g_dwT2);
    cudaGetSymbolAddress((void**)&pXs,  g_xs);
    cudaGetSymbolAddress((void**)&pQk,  g_qk);
    cudaGetSymbolAddress((void**)&pDt,  g_Dt);
    cudaGetSymbolAddress((void**)&pW,   g_W);
    cudaGetSymbolAddress((void**)&pBc,  g_bcat);
    cudaGetSymbolAddress((void**)&pPart, g_part);

    const float inv_sqrt_dk = 0.08838834764831845f;  // 1/sqrt(128)
    const float half_scale = 0.5f * inv_sqrt_dk;     // sigmoid via tanh

    prep_main<<<6400, 256>>>(x, fcw, wq, wk, wvl, wvg);   // 0
    prep_bias1<<<dim3(16, 2), 256>>>(bvl, wvg);           // 1
    prep_bias2<<<2, 768>>>(bq, bk, bvg);                  // 2

    // 3 (ncu capture slot): G0 partials = x @ fcw (2-term, K'=1024, split-K x4)
    tc_gemm<<<dim3(32, 2, 4), 256, SMEM_DYN>>>(
        pXin, 1024, 0, 512, 0, pFcw, 1024, 0, 0, 0,
        512, 256, nullptr, pPart, 256, nullptr, 0, 4, 0, 1.f);

    // wcomb: wcat rows 512.. = dw^T x wvl^T (3-term), fp16 store
    for (int l = 0; l < 2; l++)
        tc_gemm<<<dim3(2, 2, 1), 256, SMEM_DYN>>>(
            pDw + (size_t)l * 256 * 512, 512, 0, 256, 0,
            pWvl + (size_t)l * 256 * 512, 512, 0, 0, 256,
            256, 768, nullptr, nullptr, 0,
            pWc + (size_t)l * 768 * 512 + 512 * 512, 512, 1, 0, 1.f);

    ln_relu_kernel<<<4096, 256>>>(lng, lnb, fcb);

    for (int l = 0; l < 2; l++) {
        colsum_x<<<64, 256>>>();
        cvec2<<<1, 256>>>(wvl, bvl, wvg, bvg, l);

        // G1: [q|k'|D] = x @ wcat + bcat (2-term, K'=512).
        tc_gemm<<<dim3(32, 6, 1), 256, SMEM_DYN>>>(
            pXs, 512, 0, 256, 0, pWc + (size_t)l * 768 * 512, 512, 0, 0, 0,
            256, 512, pBc + l * 768, (float*)pDt, 8192, pQk, 1536, 5, 512, 1.f);

        // G2: W = sigmoid(scale * qh @ kh^T) (1-term, K'=256), tanh epilogue
        tc_gemm<<<dim3(32, 32, 1), 256, SMEM_DYN>>>(
            pQk, 1536, 0, 0, 0, pQk, 1536, 256, 256, 256,
            256, 256, nullptr, nullptr, 0, pW, 4096, 2, 0, half_scale);

        // G4: partials of W @ D (single x single, K'=4096, split-K x8)
        tc_gemm<<<dim3(32, 2, 8), 256, SMEM_DYN>>>(
            pW, 4096, 0, 0, 0, pDt, 8192, 0, 0, 0,
            4096, 512, nullptr, pPart, 256, nullptr, 0, 4, 0, 1.f);

        residual_ln_kernel<<<4096, 256>>>(lng + (l + 1) * 256, lnb + (l + 1) * 256,
                                          out, (l == 1) ? 1 : 0);
    }
}

// round 16
// speedup vs baseline: 1.1553x; 1.0489x over previous
#include <cuda_runtime.h>
#include <cuda_fp16.h>
#include <cstdint>

#define NT 4096

// ===================== device scratch (no allocs) ============================
__device__ __half g_xin2[NT * 1024];         // x input split: hi 0..511 | lo 512..1023
__device__ __half g_fcwT2[256 * 1024];       // fc_w^T split
__device__ __half g_wcatT2[2][768 * 512];    // rows: [wq(256)|wk'(256)|wcomb(256)], split cols
__device__ __half g_wvl2[2][256 * 512];      // wvl rows split (for wcomb prep GEMM)
__device__ __half g_dwT2[2][256 * 512];      // (wvg0-wvg1)^T split
__device__ float g_bcat[2][768];             // [bq | bk' | bcomb]
__device__ float g_bp[2][16][256];           // bcomb partials
__device__ __half g_xs[NT * 512];            // current x split: hi 0..255 | lo 256..511
__device__ __half g_qk[NT * 1536];           // [qh kh (unused) | lo region dead]
__device__ __half g_Dt[256 * 8192];          // D^T: hi 0..4095 (lo region dead)
__device__ __half g_W[(size_t)NT * 4096];    // sigmoid W, single fp16
__device__ float g_part[8][NT * 256];        // split-K partials
__device__ float g_cs[64 * 256];
__device__ float g_tp[8][256];               // cvec stage-1 partials
__device__ float g_cp[8][256];               // cvec stage-2 partials

// ===================== helpers ===============================================
__device__ __forceinline__ uint32_t s2u(const void* p) {
    uint32_t a;
    asm("{ .reg .u64 t; cvta.to.shared.u64 t, %1; cvt.u32.u64 %0, t; }"
        : "=r"(a) : "l"(p));
    return a;
}

#define CP_ASYNC16(saddr, gaddr) \
    asm volatile("cp.async.cg.shared.global [%0], [%1], 16;" \
                 :: "r"(saddr), "l"(gaddr) : "memory")
#define CP_COMMIT() asm volatile("cp.async.commit_group;" ::: "memory")
#define CP_WAIT1() asm volatile("cp.async.wait_group 1;" ::: "memory")

#define LDSM_X4(r0, r1, r2, r3, addr) \
    asm volatile("ldmatrix.sync.aligned.m8n8.x4.shared.b16 {%0,%1,%2,%3}, [%4];" \
                 : "=r"(r0), "=r"(r1), "=r"(r2), "=r"(r3) : "r"(addr))

#define MMA16816(d, a, b) \
    asm volatile("mma.sync.aligned.m16n8k16.row.col.f32.f16.f16.f32 " \
                 "{%0,%1,%2,%3}, {%4,%5,%6,%7}, {%8,%9}, {%0,%1,%2,%3};" \
                 : "+f"((d)[0]), "+f"((d)[1]), "+f"((d)[2]), "+f"((d)[3]) \
                 : "r"((a)[0]), "r"((a)[1]), "r"((a)[2]), "r"((a)[3]), \
                   "r"((b)[0]), "r"((b)[1]))

// ===================== fast sigmoid via tanh.approx ==========================
__device__ __forceinline__ float sigmoid_tanh(float s_halfscaled) {
    float t;
    asm("tanh.approx.f32 %0, %1;" : "=f"(t) : "f"(s_halfscaled));
    return fmaf(0.5f, t, 0.5f);
}

// ===================== generic HMMA fp16 split GEMM ==========================
// Tile 128x128, pair-stage mainloop (2x BK=32 per barrier), SIX-stage ring,
// 64B rows with XOR chunk swizzle (chunk c at c ^ ((row>>1)&3)) ->
// conflict-free ldmatrix, 16B-aligned cp.async. Depth-2 pair prefetch.
// 8 warps 2x4, warp tile 64x32, 2 CTAs/SM. kcount multiple of 64.
// modes: 0 raw fp32(+bias) -> Cf; 1 (bias?)+fp16 -> Cb; 2 sigmoid fp16 -> Cb;
// 4 fp32 partial -> Cf + z*4096*256; 5 combo: n0<nSplit mode1 else transposed.
#define TILEB (128 * 64)         // 8192
#define STAGEB (2 * TILEB)       // 16384
#define SMEM_DYN (6 * STAGEB)    // 98304

__global__ __launch_bounds__(256, 2)
void tc_gemm(const __half* __restrict__ A, int lda, int aO0, int aO1, int aO2,
             const __half* __restrict__ B, int ldb, int bO0, int bO1, int bO2,
             int Kreg, int kcount, const float* __restrict__ bias,
             float* __restrict__ Cf, int ldc,
             __half* __restrict__ Cb, int ldcb,
             int mode, int nSplit, float scale) {
    extern __shared__ __align__(16) char dsm[];
    const int tid = threadIdx.x;
    const int wid = tid >> 5, lane = tid & 31;
    const int wm = wid & 1, wn = wid >> 1;          // 2 x 4 warp grid
    const int m0 = blockIdx.x * 128, n0 = blockIdx.y * 128;
    const int kbase = blockIdx.z * kcount;
    const int P = kcount >> 6;                      // pairs of 32-K stages
    const int aO[3] = {aO0, aO1, aO2};
    const int bO[3] = {bO0, bO1, bO2};

    const uint32_t sbase = s2u(dsm);
    const int lrow = tid & 127;
    const int lc0 = tid >> 7;                       // 0 or 1
    const int lsw = (lrow >> 1) & 3;                // swizzle key for loader

    // buf in [0,6): stage buffer index
    auto load_stage = [&](int buf, int kglob) {
        int region = kglob / Kreg;
        int off = kglob - region * Kreg;
        const __half* Ap = A + (size_t)(m0 + lrow) * lda + aO[region] + off;
        const __half* Bp = B + (size_t)(n0 + lrow) * ldb + bO[region] + off;
        uint32_t sa = sbase + buf * STAGEB + lrow * 64;
        uint32_t sb = sa + TILEB;
#pragma unroll
        for (int p = 0; p < 2; p++) {
            int ch = lc0 + 2 * p;                   // 0..3
            uint32_t so = (uint32_t)((ch ^ lsw) * 16);
            CP_ASYNC16(sa + so, (const char*)(Ap + ch * 8));
            CP_ASYNC16(sb + so, (const char*)(Bp + ch * 8));
        }
    };

    float acc[4][4][4];
#pragma unroll
    for (int i = 0; i < 4; i++)
#pragma unroll
        for (int j = 0; j < 4; j++)
#pragma unroll
            for (int e = 0; e < 4; e++) acc[i][j][e] = 0.f;

    // prologue: pairs 0 and 1 (stage buffers 0..3), one commit group per pair
    load_stage(0, kbase);
    load_stage(1, kbase + 32);
    CP_COMMIT();
    if (P > 1) {
        load_stage(2, kbase + 64);
        load_stage(3, kbase + 96);
    }
    CP_COMMIT();

    // A fragment addressing (row = wm*64 + (lane&15) + mt*16; mt*16 keeps the
    // swizzle key invariant). Chunk bit0 = lane>>4, bit1 = kk.
    const int rA = wm * 64 + (lane & 15);
    const int swA = (rA >> 1) & 3;
    const uint32_t aBase = (uint32_t)rA * 64;
    const uint32_t aCk[2] = { (uint32_t)((((lane >> 4) ^ swA) & 3) * 16),
                              (uint32_t)(((((lane >> 4) ^ swA) ^ 2) & 3) * 16) };
    // B fragment addressing (rows rB and rB+16; +16 keeps key invariant).
    const int rB = wn * 32 + ((lane >> 4) << 3) + (lane & 7);
    const int swB = (rB >> 1) & 3;
    const uint32_t bBase = (uint32_t)rB * 64;
    const uint32_t bCk[2] = { (uint32_t)(((((lane >> 3) & 1) ^ swB) & 3) * 16),
                              (uint32_t)((((((lane >> 3) & 1) ^ swB) ^ 2) & 3) * 16) };

    int buf0 = 0;  // stage buffer of pair p (= (2p) % 6)
    for (int p = 0; p < P; p++) {
        CP_WAIT1();            // pair p resident (pair p+1 may still fly)
        __syncthreads();       // compute of pair p-1 done -> its buffers free
        if (p + 2 < P) {       // prefetch pair p+2 into pair (p-1)'s buffers
            int nb = buf0 + 4; if (nb >= 6) nb -= 6;
            load_stage(nb, kbase + (p + 2) * 64);
            load_stage(nb + 1, kbase + (p + 2) * 64 + 32);
        }
        CP_COMMIT();           // keep group count in lockstep with pairs
#pragma unroll
        for (int j = 0; j < 2; j++) {
            const uint32_t sa = sbase + (buf0 + j) * STAGEB;
            const uint32_t sb = sa + TILEB;
#pragma unroll
            for (int kk = 0; kk < 2; kk++) {
                uint32_t af[4][4], bf[4][2];
                LDSM_X4(bf[0][0], bf[0][1], bf[1][0], bf[1][1],
                        sb + bBase + bCk[kk]);
                LDSM_X4(bf[2][0], bf[2][1], bf[3][0], bf[3][1],
                        sb + bBase + 1024 + bCk[kk]);
#pragma unroll
                for (int mt = 0; mt < 4; mt++)
                    LDSM_X4(af[mt][0], af[mt][1], af[mt][2], af[mt][3],
                            sa + aBase + mt * 1024 + aCk[kk]);
#pragma unroll
                for (int mt = 0; mt < 4; mt++)
#pragma unroll
                    for (int nt = 0; nt < 4; nt++)
                        MMA16816(acc[mt][nt], af[mt], bf[nt]);
            }
        }
        buf0 += 2; if (buf0 >= 6) buf0 -= 6;
    }

    // ---- epilogue ----
    const int tr = lane >> 2, tc = lane & 3;
    const int mbase = m0 + wm * 64 + tr;
    const int nbase = n0 + wn * 32 + tc * 2;

    int emode = mode;
    if (mode == 5) emode = (n0 >= nSplit) ? 3 : 1;

    if (emode == 0 || emode == 4) {
        float* base = Cf + (emode == 4 ? (size_t)blockIdx.z * (4096 * 256) : 0);
#pragma unroll
        for (int mt = 0; mt < 4; mt++)
#pragma unroll
            for (int h = 0; h < 2; h++) {
                int m = mbase + mt * 16 + h * 8;
                float* rowp = base + (size_t)m * ldc;
#pragma unroll
                for (int nt = 0; nt < 4; nt++) {
                    int n = nbase + nt * 8;
                    float v0 = acc[mt][nt][2 * h + 0];
                    float v1 = acc[mt][nt][2 * h + 1];
                    if (bias) { v0 += bias[n]; v1 += bias[n + 1]; }
                    *(float2*)(rowp + n) = make_float2(v0, v1);
                }
            }
    } else if (emode == 1) {
#pragma unroll
        for (int mt = 0; mt < 4; mt++)
#pragma unroll
            for (int h = 0; h < 2; h++) {
                int m = mbase + mt * 16 + h * 8;
                __half* rowp = Cb + (size_t)m * ldcb;
#pragma unroll
                for (int nt = 0; nt < 4; nt++) {
                    int n = nbase + nt * 8;
                    float v0 = acc[mt][nt][2 * h + 0];
                    float v1 = acc[mt][nt][2 * h + 1];
                    if (bias) { v0 += bias[n]; v1 += bias[n + 1]; }
                    *(__half2*)(rowp + n) =
                        __halves2half2(__float2half_rn(v0), __float2half_rn(v1));
                }
            }
    } else if (emode == 2) {
#pragma unroll
        for (int mt = 0; mt < 4; mt++)
#pragma unroll
            for (int h = 0; h < 2; h++) {
                int m = mbase + mt * 16 + h * 8;
                __half* rowp = Cb + (size_t)m * ldcb;
#pragma unroll
                for (int nt = 0; nt < 4; nt++) {
                    int n = nbase + nt * 8;
                    float v0 = sigmoid_tanh(scale * acc[mt][nt][2 * h + 0]);
                    float v1 = sigmoid_tanh(scale * acc[mt][nt][2 * h + 1]);
                    *(__half2*)(rowp + n) =
                        __halves2half2(__float2half_rn(v0), __float2half_rn(v1));
                }
            }
    } else {  // emode 3: transposed fp16 into (half*)Cf, ld=ldc
        __half* Ct = (__half*)Cf;
#pragma unroll
        for (int mt = 0; mt < 4; mt++)
#pragma unroll
            for (int h = 0; h < 2; h++) {
                int m = mbase + mt * 16 + h * 8;
#pragma unroll
                for (int nt = 0; nt < 4; nt++) {
                    int n = nbase + nt * 8;
#pragma unroll
                    for (int e = 0; e < 2; e++) {
                        float v = acc[mt][nt][2 * h + e] + bias[n + e];
                        Ct[(size_t)(n + e - nSplit) * ldc + m] = __float2half_rn(v);
                    }
                }
            }
    }
}

// ===================== prep kernels ==========================================
__device__ __forceinline__ void split_store(__half* hi, __half* lo, float v) {
    __half h = __float2half_rn(v);
    *hi = h;
    *lo = __float2half_rn(v - __half2float(h));
}

// Segmented prep kernel. blocks: [0,4096) x | [4096,4352) fcw | [4352,5376)
// wcat | [5376,5888) wvl | [5888,6400) dw
__global__ void prep_main(const float* __restrict__ x, const float* __restrict__ fcw,
                          const float* __restrict__ wq, const float* __restrict__ wk,
                          const float* __restrict__ wvl, const float* __restrict__ wvg) {
    int b = blockIdx.x, t = threadIdx.x;
    if (b < 4096) {
        int row = b;
#pragma unroll
        for (int i = 0; i < 2; i++) {
            int c = t + i * 256;
            split_store(&g_xin2[row * 1024 + c], &g_xin2[row * 1024 + 512 + c],
                        x[row * 512 + c]);
        }
    } else if (b < 4352) {
        int n = b - 4096;
#pragma unroll
        for (int i = 0; i < 2; i++) {
            int k = t + i * 256;
            split_store(&g_fcwT2[n * 1024 + k], &g_fcwT2[n * 1024 + 512 + k],
                        fcw[k * 256 + n]);
        }
    } else if (b < 5376) {
        int idx = b - 4352, l = idx >> 9, n = idx & 511, k = t;
        float v;
        if (n < 256) v = wq[(l * 256 + k) * 256 + n];
        else {
            float s = wk[(l * 256 + k) * 256 + (n - 256)];
            v = (n - 256 < 128) ? s : -s;
        }
        split_store(&g_wcatT2[l][n * 512 + k], &g_wcatT2[l][n * 512 + 256 + k], v);
    } else if (b < 5888) {
        int idx = b - 5376, l = idx >> 8, k = idx & 255, j = t;
        float v = wvl[(l * 256 + k) * 256 + j];
        split_store(&g_wvl2[l][k * 512 + j], &g_wvl2[l][k * 512 + 256 + j], v);
    } else {
        int idx = b - 5888, l = idx >> 8, n = idx & 255, k = t;
        float v = wvg[(l * 256 + k) * 512 + n] - wvg[(l * 256 + k) * 512 + 256 + n];
        split_store(&g_dwT2[l][n * 512 + k], &g_dwT2[l][n * 512 + 256 + k], v);
    }
}

__global__ void prep_bias1(const float* __restrict__ bvl, const float* __restrict__ wvg) {
    int c = blockIdx.x, l = blockIdx.y, n = threadIdx.x;
    float acc = 0.f;
#pragma unroll
    for (int i = 0; i < 16; i++) {
        int j = c * 16 + i;
        acc += bvl[l * 256 + j] *
               (wvg[(l * 256 + j) * 512 + n] - wvg[(l * 256 + j) * 512 + 256 + n]);
    }
    g_bp[l][c][n] = acc;
}

__global__ void prep_bias2(const float* __restrict__ bq, const float* __restrict__ bk,
                           const float* __restrict__ bvg) {
    int l = blockIdx.x, t = threadIdx.x;  // 768 threads
    if (t < 256) {
        g_bcat[l][t] = bq[l * 256 + t];
    } else if (t < 512) {
        float s = bk[l * 256 + (t - 256)];
        g_bcat[l][t] = (t - 256 < 128) ? s : -s;
    } else {
        int n = t - 512;
        float acc = bvg[l * 512 + n] - bvg[l * 512 + 256 + n];
#pragma unroll
        for (int c = 0; c < 16; c++) acc += g_bp[l][c][n];
        g_bcat[l][t] = acc;
    }
}

// ===================== LN / reductions =======================================
__device__ __forceinline__ float blockSum256(float v) {
    __shared__ float sb[8];
    unsigned lane = threadIdx.x & 31, w = threadIdx.x >> 5;
#pragma unroll
    for (int o = 16; o; o >>= 1) v += __shfl_down_sync(0xffffffffu, v, o);
    if (lane == 0) sb[w] = v;
    __syncthreads();
    float r = sb[0] + sb[1] + sb[2] + sb[3] + sb[4] + sb[5] + sb[6] + sb[7];
    __syncthreads();
    return r;
}

__global__ void ln_relu_kernel(const float* __restrict__ lng, const float* __restrict__ lnb,
                               const float* __restrict__ fcb) {
    int row = blockIdx.x, d = threadIdx.x;
    size_t idx = (size_t)row * 256 + d;
    float v = g_part[0][idx] + g_part[1][idx] + g_part[2][idx] + g_part[3][idx] + fcb[d];
    float m = blockSum256(v) * (1.f / 256.f);
    float dv = v - m;
    float var = blockSum256(dv * dv) * (1.f / 256.f);
    float y = dv * rsqrtf(var + 1e-5f) * lng[d] + lnb[d];
    y = fmaxf(y, 0.f);
    split_store(&g_xs[row * 512 + d], &g_xs[row * 512 + 256 + d], y);
}

// residual LN: c[d] folded in from g_cp partials + bias term
__global__ void residual_ln_kernel(const float* __restrict__ lng, const float* __restrict__ lnb,
                                   const float* __restrict__ bvg, int l,
                                   float* __restrict__ out, int writeOut) {
    int row = blockIdx.x, d = threadIdx.x;
    size_t idx = (size_t)row * 256 + d;
    float s = 0.f;
#pragma unroll
    for (int z = 0; z < 8; z++) s += g_part[z][idx];
    float c = 4096.f * bvg[l * 512 + 256 + d];
#pragma unroll
    for (int b = 0; b < 8; b++) c += g_cp[b][d];
    float xprev = __half2float(g_xs[row * 512 + d]) +
                  __half2float(g_xs[row * 512 + 256 + d]);
    float v = 0.25f * s + 0.25f * c + 0.5f * xprev;
    float m = blockSum256(v) * (1.f / 256.f);
    float dv = v - m;
    float var = blockSum256(dv * dv) * (1.f / 256.f);
    float y = dv * rsqrtf(var + 1e-5f) * lng[d] + lnb[d];
    split_store(&g_xs[row * 512 + d], &g_xs[row * 512 + 256 + d], y);
    if (writeOut) out[idx] = y;
}

__global__ void colsum_x() {
    int b = blockIdx.x, d = threadIdx.x;
    const __half* p = g_xs + (size_t)b * 64 * 512;
    float s = 0.f;
#pragma unroll 8
    for (int r = 0; r < 64; r++)
        s += __half2float(p[r * 512 + d]) + __half2float(p[r * 512 + 256 + d]);
    g_cs[b * 256 + d] = s;
}

// cvec stage 1 (8 blocks): tp[b][j] = sum_{k in [32b,32b+32)} s[k]*wvl[k][j]
__global__ void cvec_p1(const float* __restrict__ wvl, int l) {
    __shared__ float s_sh[32];
    int b = blockIdx.x, t = threadIdx.x;
    if (t < 32) {
        int k = b * 32 + t;
        float s = 0.f;
        for (int b2 = 0; b2 < 64; b2++) s += g_cs[b2 * 256 + k];
        s_sh[t] = s;
    }
    __syncthreads();
    float acc = 0.f;
#pragma unroll 8
    for (int i = 0; i < 32; i++) {
        int k = b * 32 + i;
        acc += s_sh[i] * wvl[(l * 256 + k) * 256 + t];
    }
    g_tp[b][t] = acc;
}

// cvec stage 2 (8 blocks): t[j] = sum_b tp + N*bvl; cp[b][j] = partial over k
__global__ void cvec_p2(const float* __restrict__ bvl, const float* __restrict__ wvg, int l) {
    __shared__ float t_sh[256];
    int b = blockIdx.x, t = threadIdx.x;
    float tv = 4096.f * bvl[l * 256 + t];
#pragma unroll
    for (int b2 = 0; b2 < 8; b2++) tv += g_tp[b2][t];
    t_sh[t] = tv;
    __syncthreads();
    float acc = 0.f;
#pragma unroll 8
    for (int i = 0; i < 32; i++) {
        int k = b * 32 + i;
        acc += t_sh[k] * wvg[(l * 256 + k) * 512 + 256 + t];
    }
    g_cp[b][t] = acc;
}

// ===================== launch ================================================
extern "C" void kernel_launch(void* const* d_in, const int* in_sizes, int n_in,
                              void* d_out, int out_size) {
    const float* x   = (const float*)d_in[0];
    const float* fcw = (const float*)d_in[1];
    const float* fcb = (const float*)d_in[2];
    const float* lng = (const float*)d_in[3];
    const float* lnb = (const float*)d_in[4];
    const float* wq  = (const float*)d_in[5];
    const float* bq  = (const float*)d_in[6];
    const float* wk  = (const float*)d_in[7];
    const float* bk  = (const float*)d_in[8];
    const float* wvl = (const float*)d_in[9];
    const float* bvl = (const float*)d_in[10];
    const float* wvg = (const float*)d_in[11];
    const float* bvg = (const float*)d_in[12];
    float* out = (float*)d_out;

    static int attr_set = 0;
    if (!attr_set) {
        cudaFuncSetAttribute(tc_gemm, cudaFuncAttributeMaxDynamicSharedMemorySize, SMEM_DYN);
        cudaFuncSetAttribute(tc_gemm, cudaFuncAttributePreferredSharedMemoryCarveout, 100);
        attr_set = 1;
    }

    __half *pXin, *pFcw, *pWc, *pWvl, *pDw, *pXs, *pQk, *pDt, *pW;
    float *pBc, *pPart;
    cudaGetSymbolAddress((void**)&pXin, g_xin2);
    cudaGetSymbolAddress((void**)&pFcw, g_fcwT2);
    cudaGetSymbolAddress((void**)&pWc,  g_wcatT2);
    cudaGetSymbolAddress((void**)&pWvl, g_wvl2);
    cudaGetSymbolAddress((void**)&pDw,  g_dwT2);
    cudaGetSymbolAddress((void**)&pXs,  g_xs);
    cudaGetSymbolAddress((void**)&pQk,  g_qk);
    cudaGetSymbolAddress((void**)&pDt,  g_Dt);
    cudaGetSymbolAddress((void**)&pW,   g_W);
    cudaGetSymbolAddress((void**)&pBc,  g_bcat);
    cudaGetSymbolAddress((void**)&pPart, g_part);

    const float inv_sqrt_dk = 0.08838834764831845f;  // 1/sqrt(128)
    const float half_scale = 0.5f * inv_sqrt_dk;     // sigmoid via tanh

    prep_main<<<6400, 256>>>(x, fcw, wq, wk, wvl, wvg);   // 0
    prep_bias1<<<dim3(16, 2), 256>>>(bvl, wvg);           // 1
    prep_bias2<<<2, 768>>>(bq, bk, bvg);                  // 2

    // 3 (ncu capture slot): G0 partials = x @ fcw (2-term, K'=1024, split-K x4)
    tc_gemm<<<dim3(32, 2, 4), 256, SMEM_DYN>>>(
        pXin, 1024, 0, 512, 0, pFcw, 1024, 0, 0, 0,
        512, 256, nullptr, pPart, 256, nullptr, 0, 4, 0, 1.f);

    // wcomb: wcat rows 512.. = dw^T x wvl^T (3-term), fp16 store
    for (int l = 0; l < 2; l++)
        tc_gemm<<<dim3(2, 2, 1), 256, SMEM_DYN>>>(
            pDw + (size_t)l * 256 * 512, 512, 0, 256, 0,
            pWvl + (size_t)l * 256 * 512, 512, 0, 0, 256,
            256, 768, nullptr, nullptr, 0,
            pWc + (size_t)l * 768 * 512 + 512 * 512, 512, 1, 0, 1.f);

    ln_relu_kernel<<<4096, 256>>>(lng, lnb, fcb);

    for (int l = 0; l < 2; l++) {
        colsum_x<<<64, 256>>>();
        cvec_p1<<<8, 256>>>(wvl, l);
        cvec_p2<<<8, 256>>>(bvl, wvg, l);

        // G1: [q|k'|D] = x @ wcat + bcat (2-term, K'=512).
        tc_gemm<<<dim3(32, 6, 1), 256, SMEM_DYN>>>(
            pXs, 512, 0, 256, 0, pWc + (size_t)l * 768 * 512, 512, 0, 0, 0,
            256, 512, pBc + l * 768, (float*)pDt, 8192, pQk, 1536, 5, 512, 1.f);

        // G2: W = sigmoid(scale * qh @ kh^T) (1-term, K'=256), tanh epilogue
        tc_gemm<<<dim3(32, 32, 1), 256, SMEM_DYN>>>(
            pQk, 1536, 0, 0, 0, pQk, 1536, 256, 256, 256,
            256, 256, nullptr, nullptr, 0, pW, 4096, 2, 0, half_scale);

        // G4: partials of W @ D (single x single, K'=4096, split-K x8)
        tc_gemm<<<dim3(32, 2, 8), 256, SMEM_DYN>>>(
            pW, 4096, 0, 0, 0, pDt, 8192, 0, 0, 0,
            4096, 512, nullptr, pPart, 256, nullptr, 0, 4, 0, 1.f);

        residual_ln_kernel<<<4096, 256>>>(lng + (l + 1) * 256, lnb + (l + 1) * 256,
                                          bvg, l, out, (l == 1) ? 1 : 0);
    }
}

// round 17
// speedup vs baseline: 1.2908x; 1.1174x over previous
#include <cuda_runtime.h>
#include <cuda_fp16.h>
#include <cstdint>

#define NT 4096

// ===================== device scratch (no allocs) ============================
__device__ __half g_xin2[NT * 1024];         // x input split: hi 0..511 | lo 512..1023
__device__ __half g_fcwT2[256 * 1024];       // fc_w^T split
__device__ __half g_wcatT2[2][768 * 512];    // rows: [wq(256)|wk'(256)|wcomb(256)], split cols
__device__ __half g_wvl2[2][256 * 512];      // wvl rows split (for wcomb prep GEMM)
__device__ __half g_dwT2[2][256 * 512];      // (wvg0-wvg1)^T split
__device__ float g_bcat[2][768];             // [bq | bk' | bcomb]
__device__ float g_bp[2][16][256];           // bcomb partials
__device__ __half g_xs[NT * 512];            // current x split: hi 0..255 | lo 256..511
__device__ __half g_qk[NT * 1536];           // [qh kh (unused) | lo region dead]
__device__ __half g_Dt[256 * 8192];          // D^T: hi 0..4095 (lo region dead)
__device__ __half g_W[(size_t)NT * 4096];    // sigmoid W, single fp16
__device__ float g_part[8][NT * 256];        // split-K partials
__device__ float g_cs[64 * 256];
__device__ float g_tp[8][256];               // cvec stage-1 partials
__device__ float g_cp[8][256];               // cvec stage-2 partials

// ===================== helpers ===============================================
__device__ __forceinline__ uint32_t s2u(const void* p) {
    uint32_t a;
    asm("{ .reg .u64 t; cvta.to.shared.u64 t, %1; cvt.u32.u64 %0, t; }"
        : "=r"(a) : "l"(p));
    return a;
}

#define CP_ASYNC16(saddr, gaddr) \
    asm volatile("cp.async.cg.shared.global [%0], [%1], 16;" \
                 :: "r"(saddr), "l"(gaddr) : "memory")
#define CP_COMMIT() asm volatile("cp.async.commit_group;" ::: "memory")
#define CP_WAIT1() asm volatile("cp.async.wait_group 1;" ::: "memory")

#define LDSM_X4(r0, r1, r2, r3, addr) \
    asm volatile("ldmatrix.sync.aligned.m8n8.x4.shared.b16 {%0,%1,%2,%3}, [%4];" \
                 : "=r"(r0), "=r"(r1), "=r"(r2), "=r"(r3) : "r"(addr))

#define MMA16816(d, a, b) \
    asm volatile("mma.sync.aligned.m16n8k16.row.col.f32.f16.f16.f32 " \
                 "{%0,%1,%2,%3}, {%4,%5,%6,%7}, {%8,%9}, {%0,%1,%2,%3};" \
                 : "+f"((d)[0]), "+f"((d)[1]), "+f"((d)[2]), "+f"((d)[3]) \
                 : "r"((a)[0]), "r"((a)[1]), "r"((a)[2]), "r"((a)[3]), \
                   "r"((b)[0]), "r"((b)[1]))

// ===================== fast sigmoid via tanh.approx ==========================
__device__ __forceinline__ float sigmoid_tanh(float s_halfscaled) {
    float t;
    asm("tanh.approx.f32 %0, %1;" : "=f"(t) : "f"(s_halfscaled));
    return fmaf(0.5f, t, 0.5f);
}

// ===================== generic HMMA fp16 split GEMM ==========================
// Tile 128x128, pair-stage mainloop (2x BK=32 per barrier), SIX-stage ring,
// 64B rows with XOR chunk swizzle (chunk c at c ^ ((row>>1)&3)) ->
// conflict-free ldmatrix, 16B-aligned cp.async. Depth-2 pair prefetch.
// 8 warps 2x4, warp tile 64x32, 2 CTAs/SM. kcount multiple of 64.
// modes: 0 raw fp32(+bias) -> Cf; 1 (bias?)+fp16 -> Cb; 2 sigmoid fp16 -> Cb;
// 4 fp32 partial -> Cf + z*4096*256; 5 combo: n0<nSplit mode1 else transposed.
#define TILEB (128 * 64)         // 8192
#define STAGEB (2 * TILEB)       // 16384
#define SMEM_DYN (6 * STAGEB)    // 98304

__global__ __launch_bounds__(256, 2)
void tc_gemm(const __half* __restrict__ A, int lda, int aO0, int aO1, int aO2,
             const __half* __restrict__ B, int ldb, int bO0, int bO1, int bO2,
             int Kreg, int kcount, const float* __restrict__ bias,
             float* __restrict__ Cf, int ldc,
             __half* __restrict__ Cb, int ldcb,
             int mode, int nSplit, float scale) {
    extern __shared__ __align__(16) char dsm[];
    const int tid = threadIdx.x;
    const int wid = tid >> 5, lane = tid & 31;
    const int wm = wid & 1, wn = wid >> 1;          // 2 x 4 warp grid
    const int m0 = blockIdx.x * 128, n0 = blockIdx.y * 128;
    const int kbase = blockIdx.z * kcount;
    const int P = kcount >> 6;                      // pairs of 32-K stages
    const int aO[3] = {aO0, aO1, aO2};
    const int bO[3] = {bO0, bO1, bO2};

    const uint32_t sbase = s2u(dsm);
    const int lrow = tid & 127;
    const int lc0 = tid >> 7;                       // 0 or 1
    const int lsw = (lrow >> 1) & 3;                // swizzle key for loader

    auto load_stage = [&](int buf, int kglob) {
        int region = kglob / Kreg;
        int off = kglob - region * Kreg;
        const __half* Ap = A + (size_t)(m0 + lrow) * lda + aO[region] + off;
        const __half* Bp = B + (size_t)(n0 + lrow) * ldb + bO[region] + off;
        uint32_t sa = sbase + buf * STAGEB + lrow * 64;
        uint32_t sb = sa + TILEB;
#pragma unroll
        for (int p = 0; p < 2; p++) {
            int ch = lc0 + 2 * p;                   // 0..3
            uint32_t so = (uint32_t)((ch ^ lsw) * 16);
            CP_ASYNC16(sa + so, (const char*)(Ap + ch * 8));
            CP_ASYNC16(sb + so, (const char*)(Bp + ch * 8));
        }
    };

    float acc[4][4][4];
#pragma unroll
    for (int i = 0; i < 4; i++)
#pragma unroll
        for (int j = 0; j < 4; j++)
#pragma unroll
            for (int e = 0; e < 4; e++) acc[i][j][e] = 0.f;

    load_stage(0, kbase);
    load_stage(1, kbase + 32);
    CP_COMMIT();
    if (P > 1) {
        load_stage(2, kbase + 64);
        load_stage(3, kbase + 96);
    }
    CP_COMMIT();

    const int rA = wm * 64 + (lane & 15);
    const int swA = (rA >> 1) & 3;
    const uint32_t aBase = (uint32_t)rA * 64;
    const uint32_t aCk[2] = { (uint32_t)((((lane >> 4) ^ swA) & 3) * 16),
                              (uint32_t)(((((lane >> 4) ^ swA) ^ 2) & 3) * 16) };
    const int rB = wn * 32 + ((lane >> 4) << 3) + (lane & 7);
    const int swB = (rB >> 1) & 3;
    const uint32_t bBase = (uint32_t)rB * 64;
    const uint32_t bCk[2] = { (uint32_t)(((((lane >> 3) & 1) ^ swB) & 3) * 16),
                              (uint32_t)((((((lane >> 3) & 1) ^ swB) ^ 2) & 3) * 16) };

    int buf0 = 0;
    for (int p = 0; p < P; p++) {
        CP_WAIT1();
        __syncthreads();
        if (p + 2 < P) {
            int nb = buf0 + 4; if (nb >= 6) nb -= 6;
            load_stage(nb, kbase + (p + 2) * 64);
            load_stage(nb + 1, kbase + (p + 2) * 64 + 32);
        }
        CP_COMMIT();
#pragma unroll
        for (int j = 0; j < 2; j++) {
            const uint32_t sa = sbase + (buf0 + j) * STAGEB;
            const uint32_t sb = sa + TILEB;
#pragma unroll
            for (int kk = 0; kk < 2; kk++) {
                uint32_t af[4][4], bf[4][2];
                LDSM_X4(bf[0][0], bf[0][1], bf[1][0], bf[1][1],
                        sb + bBase + bCk[kk]);
                LDSM_X4(bf[2][0], bf[2][1], bf[3][0], bf[3][1],
                        sb + bBase + 1024 + bCk[kk]);
#pragma unroll
                for (int mt = 0; mt < 4; mt++)
                    LDSM_X4(af[mt][0], af[mt][1], af[mt][2], af[mt][3],
                            sa + aBase + mt * 1024 + aCk[kk]);
#pragma unroll
                for (int mt = 0; mt < 4; mt++)
#pragma unroll
                    for (int nt = 0; nt < 4; nt++)
                        MMA16816(acc[mt][nt], af[mt], bf[nt]);
            }
        }
        buf0 += 2; if (buf0 >= 6) buf0 -= 6;
    }

    // ---- epilogue ----
    const int tr = lane >> 2, tc = lane & 3;
    const int mbase = m0 + wm * 64 + tr;
    const int nbase = n0 + wn * 32 + tc * 2;

    int emode = mode;
    if (mode == 5) emode = (n0 >= nSplit) ? 3 : 1;

    if (emode == 0 || emode == 4) {
        float* base = Cf + (emode == 4 ? (size_t)blockIdx.z * (4096 * 256) : 0);
#pragma unroll
        for (int mt = 0; mt < 4; mt++)
#pragma unroll
            for (int h = 0; h < 2; h++) {
                int m = mbase + mt * 16 + h * 8;
                float* rowp = base + (size_t)m * ldc;
#pragma unroll
                for (int nt = 0; nt < 4; nt++) {
                    int n = nbase + nt * 8;
                    float v0 = acc[mt][nt][2 * h + 0];
                    float v1 = acc[mt][nt][2 * h + 1];
                    if (bias) { v0 += bias[n]; v1 += bias[n + 1]; }
                    *(float2*)(rowp + n) = make_float2(v0, v1);
                }
            }
    } else if (emode == 1) {
#pragma unroll
        for (int mt = 0; mt < 4; mt++)
#pragma unroll
            for (int h = 0; h < 2; h++) {
                int m = mbase + mt * 16 + h * 8;
                __half* rowp = Cb + (size_t)m * ldcb;
#pragma unroll
                for (int nt = 0; nt < 4; nt++) {
                    int n = nbase + nt * 8;
                    float v0 = acc[mt][nt][2 * h + 0];
                    float v1 = acc[mt][nt][2 * h + 1];
                    if (bias) { v0 += bias[n]; v1 += bias[n + 1]; }
                    *(__half2*)(rowp + n) =
                        __halves2half2(__float2half_rn(v0), __float2half_rn(v1));
                }
            }
    } else if (emode == 2) {
#pragma unroll
        for (int mt = 0; mt < 4; mt++)
#pragma unroll
            for (int h = 0; h < 2; h++) {
                int m = mbase + mt * 16 + h * 8;
                __half* rowp = Cb + (size_t)m * ldcb;
#pragma unroll
                for (int nt = 0; nt < 4; nt++) {
                    int n = nbase + nt * 8;
                    float v0 = sigmoid_tanh(scale * acc[mt][nt][2 * h + 0]);
                    float v1 = sigmoid_tanh(scale * acc[mt][nt][2 * h + 1]);
                    *(__half2*)(rowp + n) =
                        __halves2half2(__float2half_rn(v0), __float2half_rn(v1));
                }
            }
    } else {  // emode 3: transposed fp16 into (half*)Cf, ld=ldc
        __half* Ct = (__half*)Cf;
#pragma unroll
        for (int mt = 0; mt < 4; mt++)
#pragma unroll
            for (int h = 0; h < 2; h++) {
                int m = mbase + mt * 16 + h * 8;
#pragma unroll
                for (int nt = 0; nt < 4; nt++) {
                    int n = nbase + nt * 8;
#pragma unroll
                    for (int e = 0; e < 2; e++) {
                        float v = acc[mt][nt][2 * h + e] + bias[n + e];
                        Ct[(size_t)(n + e - nSplit) * ldc + m] = __float2half_rn(v);
                    }
                }
            }
    }
}

// ===================== prep kernels ==========================================
__device__ __forceinline__ void split_store(__half* hi, __half* lo, float v) {
    __half h = __float2half_rn(v);
    *hi = h;
    *lo = __float2half_rn(v - __half2float(h));
}

__global__ void prep_main(const float* __restrict__ x, const float* __restrict__ fcw,
                          const float* __restrict__ wq, const float* __restrict__ wk,
                          const float* __restrict__ wvl, const float* __restrict__ wvg) {
    int b = blockIdx.x, t = threadIdx.x;
    if (b < 4096) {
        int row = b;
#pragma unroll
        for (int i = 0; i < 2; i++) {
            int c = t + i * 256;
            split_store(&g_xin2[row * 1024 + c], &g_xin2[row * 1024 + 512 + c],
                        x[row * 512 + c]);
        }
    } else if (b < 4352) {
        int n = b - 4096;
#pragma unroll
        for (int i = 0; i < 2; i++) {
            int k = t + i * 256;
            split_store(&g_fcwT2[n * 1024 + k], &g_fcwT2[n * 1024 + 512 + k],
                        fcw[k * 256 + n]);
        }
    } else if (b < 5376) {
        int idx = b - 4352, l = idx >> 9, n = idx & 511, k = t;
        float v;
        if (n < 256) v = wq[(l * 256 + k) * 256 + n];
        else {
            float s = wk[(l * 256 + k) * 256 + (n - 256)];
            v = (n - 256 < 128) ? s : -s;
        }
        split_store(&g_wcatT2[l][n * 512 + k], &g_wcatT2[l][n * 512 + 256 + k], v);
    } else if (b < 5888) {
        int idx = b - 5376, l = idx >> 8, k = idx & 255, j = t;
        float v = wvl[(l * 256 + k) * 256 + j];
        split_store(&g_wvl2[l][k * 512 + j], &g_wvl2[l][k * 512 + 256 + j], v);
    } else {
        int idx = b - 5888, l = idx >> 8, n = idx & 255, k = t;
        float v = wvg[(l * 256 + k) * 512 + n] - wvg[(l * 256 + k) * 512 + 256 + n];
        split_store(&g_dwT2[l][n * 512 + k], &g_dwT2[l][n * 512 + 256 + k], v);
    }
}

__global__ void prep_bias1(const float* __restrict__ bvl, const float* __restrict__ wvg) {
    int c = blockIdx.x, l = blockIdx.y, n = threadIdx.x;
    float acc = 0.f;
#pragma unroll
    for (int i = 0; i < 16; i++) {
        int j = c * 16 + i;
        acc += bvl[l * 256 + j] *
               (wvg[(l * 256 + j) * 512 + n] - wvg[(l * 256 + j) * 512 + 256 + n]);
    }
    g_bp[l][c][n] = acc;
}

__global__ void prep_bias2(const float* __restrict__ bq, const float* __restrict__ bk,
                           const float* __restrict__ bvg) {
    int l = blockIdx.x, t = threadIdx.x;  // 768 threads
    if (t < 256) {
        g_bcat[l][t] = bq[l * 256 + t];
    } else if (t < 512) {
        float s = bk[l * 256 + (t - 256)];
        g_bcat[l][t] = (t - 256 < 128) ? s : -s;
    } else {
        int n = t - 512;
        float acc = bvg[l * 512 + n] - bvg[l * 512 + 256 + n];
#pragma unroll
        for (int c = 0; c < 16; c++) acc += g_bp[l][c][n];
        g_bcat[l][t] = acc;
    }
}

// ===================== LN / reductions =======================================
__device__ __forceinline__ float blockSum256(float v) {
    __shared__ float sb[8];
    unsigned lane = threadIdx.x & 31, w = threadIdx.x >> 5;
#pragma unroll
    for (int o = 16; o; o >>= 1) v += __shfl_down_sync(0xffffffffu, v, o);
    if (lane == 0) sb[w] = v;
    __syncthreads();
    float r = sb[0] + sb[1] + sb[2] + sb[3] + sb[4] + sb[5] + sb[6] + sb[7];
    __syncthreads();
    return r;
}

__global__ void ln_relu_kernel(const float* __restrict__ lng, const float* __restrict__ lnb,
                               const float* __restrict__ fcb) {
    int row = blockIdx.x, d = threadIdx.x;
    size_t idx = (size_t)row * 256 + d;
    float v = g_part[0][idx] + g_part[1][idx] + g_part[2][idx] + g_part[3][idx] + fcb[d];
    float m = blockSum256(v) * (1.f / 256.f);
    float dv = v - m;
    float var = blockSum256(dv * dv) * (1.f / 256.f);
    float y = dv * rsqrtf(var + 1e-5f) * lng[d] + lnb[d];
    y = fmaxf(y, 0.f);
    split_store(&g_xs[row * 512 + d], &g_xs[row * 512 + 256 + d], y);
}

__global__ void residual_ln_kernel(const float* __restrict__ lng, const float* __restrict__ lnb,
                                   const float* __restrict__ bvg, int l,
                                   float* __restrict__ out, int writeOut) {
    int row = blockIdx.x, d = threadIdx.x;
    size_t idx = (size_t)row * 256 + d;
    float s = 0.f;
#pragma unroll
    for (int z = 0; z < 8; z++) s += g_part[z][idx];
    float c = 4096.f * bvg[l * 512 + 256 + d];
#pragma unroll
    for (int b = 0; b < 8; b++) c += g_cp[b][d];
    float xprev = __half2float(g_xs[row * 512 + d]) +
                  __half2float(g_xs[row * 512 + 256 + d]);
    float v = 0.25f * s + 0.25f * c + 0.5f * xprev;
    float m = blockSum256(v) * (1.f / 256.f);
    float dv = v - m;
    float var = blockSum256(dv * dv) * (1.f / 256.f);
    float y = dv * rsqrtf(var + 1e-5f) * lng[d] + lnb[d];
    split_store(&g_xs[row * 512 + d], &g_xs[row * 512 + 256 + d], y);
    if (writeOut) out[idx] = y;
}

__global__ void colsum_x() {
    int b = blockIdx.x, d = threadIdx.x;
    const __half* p = g_xs + (size_t)b * 64 * 512;
    float s = 0.f;
#pragma unroll 8
    for (int r = 0; r < 64; r++)
        s += __half2float(p[r * 512 + d]) + __half2float(p[r * 512 + 256 + d]);
    g_cs[b * 256 + d] = s;
}

__global__ void cvec_p1(const float* __restrict__ wvl, int l) {
    __shared__ float s_sh[32];
    int b = blockIdx.x, t = threadIdx.x;
    if (t < 32) {
        int k = b * 32 + t;
        float s = 0.f;
        for (int b2 = 0; b2 < 64; b2++) s += g_cs[b2 * 256 + k];
        s_sh[t] = s;
    }
    __syncthreads();
    float acc = 0.f;
#pragma unroll 8
    for (int i = 0; i < 32; i++) {
        int k = b * 32 + i;
        acc += s_sh[i] * wvl[(l * 256 + k) * 256 + t];
    }
    g_tp[b][t] = acc;
}

__global__ void cvec_p2(const float* __restrict__ bvl, const float* __restrict__ wvg, int l) {
    __shared__ float t_sh[256];
    int b = blockIdx.x, t = threadIdx.x;
    float tv = 4096.f * bvl[l * 256 + t];
#pragma unroll
    for (int b2 = 0; b2 < 8; b2++) tv += g_tp[b2][t];
    t_sh[t] = tv;
    __syncthreads();
    float acc = 0.f;
#pragma unroll 8
    for (int i = 0; i < 32; i++) {
        int k = b * 32 + i;
        acc += t_sh[k] * wvg[(l * 256 + k) * 512 + 256 + t];
    }
    g_cp[b][t] = acc;
}

// ===================== launch ================================================
extern "C" void kernel_launch(void* const* d_in, const int* in_sizes, int n_in,
                              void* d_out, int out_size) {
    const float* x   = (const float*)d_in[0];
    const float* fcw = (const float*)d_in[1];
    const float* fcb = (const float*)d_in[2];
    const float* lng = (const float*)d_in[3];
    const float* lnb = (const float*)d_in[4];
    const float* wq  = (const float*)d_in[5];
    const float* bq  = (const float*)d_in[6];
    const float* wk  = (const float*)d_in[7];
    const float* bk  = (const float*)d_in[8];
    const float* wvl = (const float*)d_in[9];
    const float* bvl = (const float*)d_in[10];
    const float* wvg = (const float*)d_in[11];
    const float* bvg = (const float*)d_in[12];
    float* out = (float*)d_out;

    static int attr_set = 0;
    static cudaStream_t s2;
    static cudaEvent_t evFork, evJoin;
    if (!attr_set) {
        cudaFuncSetAttribute(tc_gemm, cudaFuncAttributeMaxDynamicSharedMemorySize, SMEM_DYN);
        cudaFuncSetAttribute(tc_gemm, cudaFuncAttributePreferredSharedMemoryCarveout, 100);
        cudaStreamCreateWithFlags(&s2, cudaStreamNonBlocking);
        cudaEventCreateWithFlags(&evFork, cudaEventDisableTiming);
        cudaEventCreateWithFlags(&evJoin, cudaEventDisableTiming);
        attr_set = 1;
    }

    __half *pXin, *pFcw, *pWc, *pWvl, *pDw, *pXs, *pQk, *pDt, *pW;
    float *pBc, *pPart;
    cudaGetSymbolAddress((void**)&pXin, g_xin2);
    cudaGetSymbolAddress((void**)&pFcw, g_fcwT2);
    cudaGetSymbolAddress((void**)&pWc,  g_wcatT2);
    cudaGetSymbolAddress((void**)&pWvl, g_wvl2);
    cudaGetSymbolAddress((void**)&pDw,  g_dwT2);
    cudaGetSymbolAddress((void**)&pXs,  g_xs);
    cudaGetSymbolAddress((void**)&pQk,  g_qk);
    cudaGetSymbolAddress((void**)&pDt,  g_Dt);
    cudaGetSymbolAddress((void**)&pW,   g_W);
    cudaGetSymbolAddress((void**)&pBc,  g_bcat);
    cudaGetSymbolAddress((void**)&pPart, g_part);

    const float inv_sqrt_dk = 0.08838834764831845f;  // 1/sqrt(128)
    const float half_scale = 0.5f * inv_sqrt_dk;     // sigmoid via tanh

    prep_main<<<6400, 256>>>(x, fcw, wq, wk, wvl, wvg);

    // ---- fork: side stream does bias prep + wcomb while main does G0 ----
    cudaEventRecord(evFork, 0);
    cudaStreamWaitEvent(s2, evFork, 0);
    prep_bias1<<<dim3(16, 2), 256, 0, s2>>>(bvl, wvg);
    prep_bias2<<<2, 768, 0, s2>>>(bq, bk, bvg);
    for (int l = 0; l < 2; l++)
        tc_gemm<<<dim3(2, 2, 1), 256, SMEM_DYN, s2>>>(
            pDw + (size_t)l * 256 * 512, 512, 0, 256, 0,
            pWvl + (size_t)l * 256 * 512, 512, 0, 0, 256,
            256, 768, nullptr, nullptr, 0,
            pWc + (size_t)l * 768 * 512 + 512 * 512, 512, 1, 0, 1.f);
    cudaEventRecord(evJoin, s2);

    // main: G0 (2-term, K'=1024, split-K x4) + ln_relu
    tc_gemm<<<dim3(32, 2, 4), 256, SMEM_DYN>>>(
        pXin, 1024, 0, 512, 0, pFcw, 1024, 0, 0, 0,
        512, 256, nullptr, pPart, 256, nullptr, 0, 4, 0, 1.f);
    ln_relu_kernel<<<4096, 256>>>(lng, lnb, fcb);
    cudaStreamWaitEvent(0, evJoin, 0);   // wcat/bcat ready before G1

    for (int l = 0; l < 2; l++) {
        // ---- fork: cvec chain runs beside G1/G2/G4 ----
        cudaEventRecord(evFork, 0);
        cudaStreamWaitEvent(s2, evFork, 0);
        colsum_x<<<64, 256, 0, s2>>>();
        cvec_p1<<<8, 256, 0, s2>>>(wvl, l);
        cvec_p2<<<8, 256, 0, s2>>>(bvl, wvg, l);
        cudaEventRecord(evJoin, s2);

        // G1: [q|k'|D] = x @ wcat + bcat (2-term, K'=512).
        tc_gemm<<<dim3(32, 6, 1), 256, SMEM_DYN>>>(
            pXs, 512, 0, 256, 0, pWc + (size_t)l * 768 * 512, 512, 0, 0, 0,
            256, 512, pBc + l * 768, (float*)pDt, 8192, pQk, 1536, 5, 512, 1.f);

        // G2: W = sigmoid(scale * qh @ kh^T) (1-term, K'=256), tanh epilogue
        tc_gemm<<<dim3(32, 32, 1), 256, SMEM_DYN>>>(
            pQk, 1536, 0, 0, 0, pQk, 1536, 256, 256, 256,
            256, 256, nullptr, nullptr, 0, pW, 4096, 2, 0, half_scale);

        // G4: partials of W @ D (single x single, K'=4096, split-K x8)
        tc_gemm<<<dim3(32, 2, 8), 256, SMEM_DYN>>>(
            pW, 4096, 0, 0, 0, pDt, 8192, 0, 0, 0,
            4096, 512, nullptr, pPart, 256, nullptr, 0, 4, 0, 1.f);

        cudaStreamWaitEvent(0, evJoin, 0);  // g_cp ready
        residual_ln_kernel<<<4096, 256>>>(lng + (l + 1) * 256, lnb + (l + 1) * 256,
                                          bvg, l, out, (l == 1) ? 1 : 0);
    }
}